// round 1
// baseline (speedup 1.0000x reference)
#include <cuda_runtime.h>
#include <cstdint>

#define BB 64
#define PP 25000
#define TT 16
#define CC 81

// ---------------- scratch (static __device__, no allocs) ----------------
__device__ float               g_bt_ov[BB * PP];       // best truth overlap per prior
__device__ unsigned char       g_bt_idx[BB * PP];      // best truth index per prior
__device__ unsigned long long  g_bp_key[BB * TT];      // packed (iou_bits<<32 | ~p) per truth
__device__ float               g_loss_c[BB * PP];      // pos ? 0 : ce
__device__ int                 g_num_pos[BB];
__device__ int                 g_total_pos;
__device__ double              g_loss_l;
__device__ double              g_ce_pos;
__device__ double              g_ce_neg;

// ---------------- init ----------------
__global__ void init_kernel() {
    int i = threadIdx.x + blockIdx.x * blockDim.x;
    if (i < BB * TT) g_bp_key[i] = 0ULL;
    if (i < BB)      g_num_pos[i] = 0;
    if (i == 0) { g_total_pos = 0; g_loss_l = 0.0; g_ce_pos = 0.0; g_ce_neg = 0.0; }
}

// ---------------- match: per-prior best truth + per-truth best prior ----------------
__global__ void match_kernel(const float* __restrict__ priors,
                             const float* __restrict__ targets) {
    const int b = blockIdx.y;
    const int p = blockIdx.x * 256 + threadIdx.x;
    __shared__ float s_t[TT][4];
    __shared__ float s_ta[TT];
    __shared__ unsigned long long s_key[TT];

    if (threadIdx.x < TT) {
        const float* tr = targets + ((size_t)b * TT + threadIdx.x) * 5;
        float x0 = tr[0], y0 = tr[1], x1 = tr[2], y1 = tr[3];
        s_t[threadIdx.x][0] = x0; s_t[threadIdx.x][1] = y0;
        s_t[threadIdx.x][2] = x1; s_t[threadIdx.x][3] = y1;
        s_ta[threadIdx.x] = (x1 - x0) * (y1 - y0);
        s_key[threadIdx.x] = 0ULL;
    }
    __syncthreads();

    const bool valid = (p < PP);
    float px0 = 0.f, py0 = 0.f, px1 = 0.f, py1 = 0.f, pa = 0.f;
    if (valid) {
        float4 pr = ((const float4*)priors)[p];
        px0 = pr.x - pr.z * 0.5f; py0 = pr.y - pr.w * 0.5f;
        px1 = pr.x + pr.z * 0.5f; py1 = pr.y + pr.w * 0.5f;
        pa  = (px1 - px0) * (py1 - py0);  // area from point form, matches reference
    }

    float best = -1.0f;
    int   bi   = 0;

    #pragma unroll
    for (int t = 0; t < TT; t++) {
        float iou = 0.0f;
        if (valid) {
            float lx = fmaxf(s_t[t][0], px0), ly = fmaxf(s_t[t][1], py0);
            float rx = fminf(s_t[t][2], px1), ry = fminf(s_t[t][3], py1);
            float iw = fmaxf(rx - lx, 0.0f), ih = fmaxf(ry - ly, 0.0f);
            float inter = iw * ih;
            iou = inter / (s_ta[t] + pa - inter);
            if (iou > best) { best = iou; bi = t; }   // strict > -> first max (jnp.argmax axis=0)
        }
        // pack: higher iou wins; on tie smaller p wins (first-index jnp.argmax axis=1)
        unsigned long long key = valid
            ? ((((unsigned long long)__float_as_uint(iou)) << 32) | (unsigned)(~(unsigned)p))
            : 0ULL;
        #pragma unroll
        for (int o = 16; o > 0; o >>= 1) {
            unsigned long long other = __shfl_down_sync(0xffffffffu, key, o);
            key = (other > key) ? other : key;
        }
        if ((threadIdx.x & 31) == 0) atomicMax(&s_key[t], key);
    }

    if (valid) {
        g_bt_ov[(size_t)b * PP + p]  = best;
        g_bt_idx[(size_t)b * PP + p] = (unsigned char)bi;
    }
    __syncthreads();
    if (threadIdx.x < TT) atomicMax(&g_bp_key[b * TT + threadIdx.x], s_key[threadIdx.x]);
}

// ---------------- fused loss: match finalize + smooth-L1 + logsumexp CE ----------------
// warp per prior (coalesced 81-float row reads)
__global__ void loss_kernel(const float* __restrict__ loc_data,
                            const float* __restrict__ conf_data,
                            const float* __restrict__ priors,
                            const float* __restrict__ targets) {
    const int b    = blockIdx.y;
    const int lane = threadIdx.x & 31;
    const int warp = threadIdx.x >> 5;
    const int p    = blockIdx.x * 8 + warp;

    __shared__ int   s_bpi[TT];
    __shared__ float s_tr[TT][5];
    if (threadIdx.x < TT)
        s_bpi[threadIdx.x] = (int)(~(unsigned)(g_bp_key[b * TT + threadIdx.x] & 0xFFFFFFFFULL));
    if (threadIdx.x < TT * 5)
        ((float*)s_tr)[threadIdx.x] = targets[(size_t)b * TT * 5 + threadIdx.x];
    __syncthreads();

    float my_ll = 0.f, my_cep = 0.f;
    int   my_pos = 0;

    if (p < PP) {
        float ov = g_bt_ov[(size_t)b * PP + p];
        int   ti = g_bt_idx[(size_t)b * PP + p];
        #pragma unroll
        for (int j = 0; j < TT; j++) {
            if (s_bpi[j] == p) { ov = 2.0f; ti = j; }   // ascending j -> last wins
        }
        bool pos = (ov >= 0.5f);
        int  ct  = pos ? ((int)s_tr[ti][4] + 1) : 0;

        const float* row = conf_data + ((size_t)b * PP + p) * CC;
        float v0 = row[lane];
        float v1 = row[32 + lane];
        float v2 = (lane < CC - 64) ? row[64 + lane] : -3.0e38f;

        float m = fmaxf(v0, fmaxf(v1, v2));
        #pragma unroll
        for (int o = 16; o > 0; o >>= 1) m = fmaxf(m, __shfl_xor_sync(0xffffffffu, m, o));
        float s = __expf(v0 - m) + __expf(v1 - m) + ((lane < CC - 64) ? __expf(v2 - m) : 0.f);
        #pragma unroll
        for (int o = 16; o > 0; o >>= 1) s += __shfl_xor_sync(0xffffffffu, s, o);
        float lse = m + __logf(s);

        float cg = -3.0e38f;
        if (ct == lane)           cg = v0;
        else if (ct == 32 + lane) cg = v1;
        else if (ct == 64 + lane) cg = v2;
        #pragma unroll
        for (int o = 16; o > 0; o >>= 1) cg = fmaxf(cg, __shfl_xor_sync(0xffffffffu, cg, o));

        float ce = lse - cg;

        if (lane == 0) {
            g_loss_c[(size_t)b * PP + p] = pos ? 0.0f : ce;
            if (pos) {
                my_pos = 1;
                my_cep = ce;
                float4 pr = ((const float4*)priors)[p];
                float tx0 = s_tr[ti][0], ty0 = s_tr[ti][1];
                float tx1 = s_tr[ti][2], ty1 = s_tr[ti][3];
                float gx = ((tx0 + tx1) * 0.5f - pr.x) / (0.1f * pr.z);
                float gy = ((ty0 + ty1) * 0.5f - pr.y) / (0.1f * pr.w);
                float gw = __logf((tx1 - tx0) / pr.z) * 5.0f;
                float gh = __logf((ty1 - ty0) / pr.w) * 5.0f;
                float4 ld = ((const float4*)loc_data)[(size_t)b * PP + p];
                float d, ad;
                d = ld.x - gx; ad = fabsf(d); my_ll += (ad < 1.f) ? 0.5f * d * d : ad - 0.5f;
                d = ld.y - gy; ad = fabsf(d); my_ll += (ad < 1.f) ? 0.5f * d * d : ad - 0.5f;
                d = ld.z - gw; ad = fabsf(d); my_ll += (ad < 1.f) ? 0.5f * d * d : ad - 0.5f;
                d = ld.w - gh; ad = fabsf(d); my_ll += (ad < 1.f) ? 0.5f * d * d : ad - 0.5f;
            }
        }
    }

    // block reduce (only lane0 of each warp holds nonzero, but reduce generally)
    #pragma unroll
    for (int o = 16; o > 0; o >>= 1) {
        my_ll  += __shfl_xor_sync(0xffffffffu, my_ll, o);
        my_cep += __shfl_xor_sync(0xffffffffu, my_cep, o);
        my_pos += __shfl_xor_sync(0xffffffffu, my_pos, o);
    }
    __shared__ float s_ll[8], s_cep[8];
    __shared__ int   s_pos[8];
    if (lane == 0) { s_ll[warp] = my_ll; s_cep[warp] = my_cep; s_pos[warp] = my_pos; }
    __syncthreads();
    if (threadIdx.x == 0) {
        float ll = 0.f, cep = 0.f; int np = 0;
        #pragma unroll
        for (int w = 0; w < 8; w++) { ll += s_ll[w]; cep += s_cep[w]; np += s_pos[w]; }
        if (ll  != 0.f) atomicAdd(&g_loss_l, (double)ll);
        if (cep != 0.f) atomicAdd(&g_ce_pos, (double)cep);
        if (np) { atomicAdd(&g_num_pos[b], np); atomicAdd(&g_total_pos, np); }
    }
}

// ---------------- hard-negative mining: exact radix-select top-k sum ----------------
__global__ void mine_kernel() {
    const int b   = blockIdx.x;
    const int tid = threadIdx.x;
    __shared__ int      hist[256];
    __shared__ unsigned s_prefix;
    __shared__ int      s_kk;

    int np = g_num_pos[b];
    int k  = min(3 * np, PP - 1);
    if (k <= 0) return;  // uniform across block

    const float* lc = g_loss_c + (size_t)b * PP;
    unsigned prefix = 0;
    int kk = k;

    for (int shift = 24; shift >= 0; shift -= 8) {
        unsigned pmask = (shift == 24) ? 0u : (0xFFFFFFFFu << (shift + 8));
        if (tid < 256) hist[tid] = 0;
        __syncthreads();
        for (int i = tid; i < PP; i += blockDim.x) {
            unsigned key = __float_as_uint(lc[i]);   // all values >= 0 -> order-preserving bits
            if ((key & pmask) == prefix) atomicAdd(&hist[(key >> shift) & 255], 1);
        }
        __syncthreads();
        if (tid == 0) {
            int cum = 0, bin = 0, rem = kk;
            for (int x = 255; x >= 0; x--) {
                int h = hist[x];
                if (cum + h >= kk) { bin = x; rem = kk - cum; break; }
                cum += h;
            }
            s_prefix = prefix | ((unsigned)bin << shift);
            s_kk = rem;
        }
        __syncthreads();
        prefix = s_prefix;
        kk     = s_kk;
    }

    float  thr   = __uint_as_float(prefix);
    double local = 0.0;
    for (int i = tid; i < PP; i += blockDim.x) {
        float v = lc[i];
        if (__float_as_uint(v) > prefix) local += (double)v;
    }
    #pragma unroll
    for (int o = 16; o > 0; o >>= 1) local += __shfl_xor_sync(0xffffffffu, local, o);
    __shared__ double sdl[32];
    int lane = tid & 31, w = tid >> 5;
    if (lane == 0) sdl[w] = local;
    __syncthreads();
    if (tid == 0) {
        double tot = 0.0;
        for (int i = 0; i < (int)(blockDim.x >> 5); i++) tot += sdl[i];
        tot += (double)kk * (double)thr;   // tie-filled remainder: value-identical
        atomicAdd(&g_ce_neg, tot);
    }
}

// ---------------- finalize ----------------
__global__ void final_kernel(float* out) {
    double N = (double)g_total_pos;
    if (N < 1.0) N = 1.0;
    out[0] = (float)(g_loss_l / N);
    out[1] = (float)((g_ce_pos + g_ce_neg) / N);
}

extern "C" void kernel_launch(void* const* d_in, const int* in_sizes, int n_in,
                              void* d_out, int out_size) {
    const float* loc_data  = (const float*)d_in[0];   // [B,P,4]
    const float* conf_data = (const float*)d_in[1];   // [B,P,81]
    const float* priors    = (const float*)d_in[2];   // [P,4]
    const float* targets   = (const float*)d_in[3];   // [B,T,5]
    float* out = (float*)d_out;

    init_kernel<<<(BB * TT + 255) / 256, 256>>>();
    match_kernel<<<dim3((PP + 255) / 256, BB), 256>>>(priors, targets);
    loss_kernel<<<dim3((PP + 7) / 8, BB), 256>>>(loc_data, conf_data, priors, targets);
    mine_kernel<<<BB, 1024>>>();
    final_kernel<<<1, 1>>>(out);
}

// round 2
// speedup vs baseline: 1.7121x; 1.7121x over previous
#include <cuda_runtime.h>
#include <cstdint>

#define BB 64
#define PP 25000
#define TT 16
#define CC 81

// ---------------- scratch ----------------
__device__ float               g_bt_ov[BB * PP];
__device__ unsigned char       g_bt_idx[BB * PP];
__device__ unsigned long long  g_bp_key[BB * TT];
__device__ float               g_loss_c[BB * PP];
__device__ int                 g_num_pos[BB];
__device__ int                 g_total_pos;
__device__ double              g_loss_l;
__device__ double              g_ce_pos;
__device__ double              g_ce_neg;

// ---------------- init ----------------
__global__ void init_kernel() {
    int i = threadIdx.x;
    if (i < BB * TT) g_bp_key[i] = 0ULL;
    if (i < BB)      g_num_pos[i] = 0;
    if (i == 0) { g_total_pos = 0; g_loss_l = 0.0; g_ce_pos = 0.0; g_ce_neg = 0.0; }
}

// ---------------- match ----------------
__global__ void match_kernel(const float* __restrict__ priors,
                             const float* __restrict__ targets) {
    const int b = blockIdx.y;
    const int p = blockIdx.x * 256 + threadIdx.x;
    const int lane = threadIdx.x & 31;
    __shared__ float s_t[TT][4];
    __shared__ float s_ta[TT];
    __shared__ unsigned long long s_key[TT];

    if (threadIdx.x < TT) {
        const float* tr = targets + ((size_t)b * TT + threadIdx.x) * 5;
        float x0 = tr[0], y0 = tr[1], x1 = tr[2], y1 = tr[3];
        s_t[threadIdx.x][0] = x0; s_t[threadIdx.x][1] = y0;
        s_t[threadIdx.x][2] = x1; s_t[threadIdx.x][3] = y1;
        s_ta[threadIdx.x] = (x1 - x0) * (y1 - y0);
        s_key[threadIdx.x] = 0ULL;
    }
    __syncthreads();

    const bool valid = (p < PP);
    float px0 = 0.f, py0 = 0.f, px1 = 0.f, py1 = 0.f, pa = 0.f;
    if (valid) {
        float4 pr = ((const float4*)priors)[p];
        px0 = pr.x - pr.z * 0.5f; py0 = pr.y - pr.w * 0.5f;
        px1 = pr.x + pr.z * 0.5f; py1 = pr.y + pr.w * 0.5f;
        pa  = (px1 - px0) * (py1 - py0);
    }

    float best = -1.0f;
    int   bi   = 0;

    #pragma unroll
    for (int t = 0; t < TT; t++) {
        float iou = -1.0f;
        if (valid) {
            float lx = fmaxf(s_t[t][0], px0), ly = fmaxf(s_t[t][1], py0);
            float rx = fminf(s_t[t][2], px1), ry = fminf(s_t[t][3], py1);
            float iw = fmaxf(rx - lx, 0.0f), ih = fmaxf(ry - ly, 0.0f);
            float inter = iw * ih;
            iou = inter / (s_ta[t] + pa - inter);
            if (iou > best) { best = iou; bi = t; }   // strict > -> first max
        }
        // warp max (32-bit), leader = lowest lane with max = smallest p
        float wmax = iou;
        #pragma unroll
        for (int o = 16; o > 0; o >>= 1)
            wmax = fmaxf(wmax, __shfl_xor_sync(0xffffffffu, wmax, o));
        unsigned ball = __ballot_sync(0xffffffffu, valid && (iou == wmax));
        if (ball != 0 && lane == (__ffs(ball) - 1)) {
            unsigned long long key =
                (((unsigned long long)__float_as_uint(iou)) << 32) | (unsigned)(~(unsigned)p);
            atomicMax(&s_key[t], key);
        }
    }

    if (valid) {
        g_bt_ov[(size_t)b * PP + p]  = best;
        g_bt_idx[(size_t)b * PP + p] = (unsigned char)bi;
    }
    __syncthreads();
    if (threadIdx.x < TT) atomicMax(&g_bp_key[b * TT + threadIdx.x], s_key[threadIdx.x]);
}

// ---------------- force each truth's best prior (last j wins) ----------------
__global__ void force_kernel() {
    int b = threadIdx.x;
    if (b >= BB) return;
    for (int j = 0; j < TT; j++) {
        unsigned long long key = g_bp_key[b * TT + j];
        unsigned p = ~(unsigned)(key & 0xFFFFFFFFULL);
        g_bt_ov[(size_t)b * PP + p]  = 2.0f;
        g_bt_idx[(size_t)b * PP + p] = (unsigned char)j;
    }
}

// ---------------- fused loss: 4 priors per warp ----------------
__global__ void loss_kernel(const float* __restrict__ loc_data,
                            const float* __restrict__ conf_data,
                            const float* __restrict__ priors,
                            const float* __restrict__ targets) {
    const int b    = blockIdx.y;
    const int lane = threadIdx.x & 31;
    const int warp = threadIdx.x >> 5;
    const int p0   = (blockIdx.x * 8 + warp) * 4;

    __shared__ float s_tr[TT][5];
    if (threadIdx.x < TT * 5)
        ((float*)s_tr)[threadIdx.x] = targets[(size_t)b * TT * 5 + threadIdx.x];
    __syncthreads();

    float my_ll = 0.f, my_cep = 0.f;
    int   my_pos = 0;

    const bool active = (p0 < PP);
    if (active) {
        const float* base = conf_data + ((size_t)b * PP + p0) * CC;
        // front-batched loads for MLP
        float v0[4], v1[4], v2[4];
        #pragma unroll
        for (int q = 0; q < 4; q++) {
            const float* row = base + q * CC;
            v0[q] = __ldcs(row + lane);
            v1[q] = __ldcs(row + 32 + lane);
            v2[q] = (lane < CC - 64) ? __ldcs(row + 64 + lane) : 0.f;
        }

        float lc[4];
        float4 ovs;
        uchar4 tis;
        if (lane == 0) {
            ovs = *(const float4*)(g_bt_ov + (size_t)b * PP + p0);
            tis = *(const uchar4*)(g_bt_idx + (size_t)b * PP + p0);
        }

        #pragma unroll
        for (int q = 0; q < 4; q++) {
            float e = __expf(v0[q]) + __expf(v1[q]);
            if (lane < CC - 64) e += __expf(v2[q]);
            #pragma unroll
            for (int o = 16; o > 0; o >>= 1) e += __shfl_xor_sync(0xffffffffu, e, o);

            if (lane == 0) {
                float lse = __logf(e);
                float ov = (q == 0) ? ovs.x : (q == 1) ? ovs.y : (q == 2) ? ovs.z : ovs.w;
                int   ti = (q == 0) ? tis.x : (q == 1) ? tis.y : (q == 2) ? tis.z : tis.w;
                bool pos = (ov >= 0.5f);
                int  ct  = pos ? ((int)s_tr[ti][4] + 1) : 0;
                float cg = base[q * CC + ct];          // L1 hit
                float ce = lse - cg;
                lc[q] = pos ? 0.f : ce;
                if (pos) {
                    my_pos++;
                    my_cep += ce;
                    int p = p0 + q;
                    float4 pr = ((const float4*)priors)[p];
                    float tx0 = s_tr[ti][0], ty0 = s_tr[ti][1];
                    float tx1 = s_tr[ti][2], ty1 = s_tr[ti][3];
                    float gx = ((tx0 + tx1) * 0.5f - pr.x) / (0.1f * pr.z);
                    float gy = ((ty0 + ty1) * 0.5f - pr.y) / (0.1f * pr.w);
                    float gw = __logf((tx1 - tx0) / pr.z) * 5.0f;
                    float gh = __logf((ty1 - ty0) / pr.w) * 5.0f;
                    float4 ld = ((const float4*)loc_data)[(size_t)b * PP + p];
                    float d, ad;
                    d = ld.x - gx; ad = fabsf(d); my_ll += (ad < 1.f) ? 0.5f * d * d : ad - 0.5f;
                    d = ld.y - gy; ad = fabsf(d); my_ll += (ad < 1.f) ? 0.5f * d * d : ad - 0.5f;
                    d = ld.z - gw; ad = fabsf(d); my_ll += (ad < 1.f) ? 0.5f * d * d : ad - 0.5f;
                    d = ld.w - gh; ad = fabsf(d); my_ll += (ad < 1.f) ? 0.5f * d * d : ad - 0.5f;
                }
            }
        }
        if (lane == 0)
            *(float4*)(g_loss_c + (size_t)b * PP + p0) = make_float4(lc[0], lc[1], lc[2], lc[3]);
    }

    // epilogue: lane0 values only
    __shared__ float s_ll[8], s_cep[8];
    __shared__ int   s_pos[8];
    if (lane == 0) { s_ll[warp] = my_ll; s_cep[warp] = my_cep; s_pos[warp] = my_pos; }
    __syncthreads();
    if (threadIdx.x == 0) {
        float ll = 0.f, cep = 0.f; int np = 0;
        #pragma unroll
        for (int w = 0; w < 8; w++) { ll += s_ll[w]; cep += s_cep[w]; np += s_pos[w]; }
        if (np) {
            atomicAdd(&g_loss_l, (double)ll);
            atomicAdd(&g_ce_pos, (double)cep);
            atomicAdd(&g_num_pos[b], np);
            atomicAdd(&g_total_pos, np);
        }
    }
}

// ---------------- hard-negative mining: 3-pass radix select + sum ----------------
__global__ void mine_kernel() {
    const int b   = blockIdx.x;
    const int tid = threadIdx.x;
    __shared__ int      hist[2048];
    __shared__ int      s_group[64];
    __shared__ unsigned s_prefix;
    __shared__ int      s_kk;

    int np = g_num_pos[b];
    int k  = min(3 * np, PP - 1);
    if (k <= 0) return;  // uniform across block

    const float* lc = g_loss_c + (size_t)b * PP;
    unsigned prefix = 0;
    int kk = k;

    const int shifts[3] = {21, 10, 0};
    const int nbits [3] = {11, 11, 10};

    #pragma unroll
    for (int pass = 0; pass < 3; pass++) {
        const int shift = shifts[pass];
        const int nb    = 1 << nbits[pass];
        hist[tid] = 0; hist[tid + 1024] = 0;
        __syncthreads();
        const unsigned hmask = (pass == 0) ? 0u : (0xFFFFFFFFu << (shift + nbits[pass]));
        const unsigned bmask = (unsigned)(nb - 1);

        int i = tid;
        for (; i + 3 * 1024 < PP; i += 4 * 1024) {
            unsigned k0 = __float_as_uint(lc[i]);
            unsigned k1 = __float_as_uint(lc[i + 1024]);
            unsigned k2 = __float_as_uint(lc[i + 2048]);
            unsigned k3 = __float_as_uint(lc[i + 3072]);
            if ((k0 & hmask) == prefix) atomicAdd(&hist[(k0 >> shift) & bmask], 1);
            if ((k1 & hmask) == prefix) atomicAdd(&hist[(k1 >> shift) & bmask], 1);
            if ((k2 & hmask) == prefix) atomicAdd(&hist[(k2 >> shift) & bmask], 1);
            if ((k3 & hmask) == prefix) atomicAdd(&hist[(k3 >> shift) & bmask], 1);
        }
        for (; i < PP; i += 1024) {
            unsigned key = __float_as_uint(lc[i]);
            if ((key & hmask) == prefix) atomicAdd(&hist[(key >> shift) & bmask], 1);
        }
        __syncthreads();

        const int ngroups = nb >> 5;
        if (tid < ngroups) {
            int s = 0;
            #pragma unroll
            for (int j = 0; j < 32; j++) s += hist[tid * 32 + j];
            s_group[tid] = s;
        }
        __syncthreads();
        if (tid == 0) {
            int cum = 0, g = ngroups - 1;
            for (; g > 0; g--) {
                if (cum + s_group[g] >= kk) break;
                cum += s_group[g];
            }
            int x = g * 32 + 31;
            for (;; x--) {
                int h = hist[x];
                if (cum + h >= kk || x == g * 32) break;
                cum += h;
            }
            s_prefix = prefix | ((unsigned)x << shift);
            s_kk = kk - cum;
        }
        __syncthreads();
        prefix = s_prefix;
        kk     = s_kk;
    }

    float  thr   = __uint_as_float(prefix);
    double local = 0.0;
    {
        int i = tid;
        for (; i + 3 * 1024 < PP; i += 4 * 1024) {
            float a0 = lc[i], a1 = lc[i + 1024], a2 = lc[i + 2048], a3 = lc[i + 3072];
            if (__float_as_uint(a0) > prefix) local += (double)a0;
            if (__float_as_uint(a1) > prefix) local += (double)a1;
            if (__float_as_uint(a2) > prefix) local += (double)a2;
            if (__float_as_uint(a3) > prefix) local += (double)a3;
        }
        for (; i < PP; i += 1024) {
            float v = lc[i];
            if (__float_as_uint(v) > prefix) local += (double)v;
        }
    }
    #pragma unroll
    for (int o = 16; o > 0; o >>= 1) local += __shfl_xor_sync(0xffffffffu, local, o);
    __shared__ double sdl[32];
    int lane = tid & 31, w = tid >> 5;
    if (lane == 0) sdl[w] = local;
    __syncthreads();
    if (tid == 0) {
        double tot = 0.0;
        for (int i = 0; i < 32; i++) tot += sdl[i];
        tot += (double)kk * (double)thr;
        atomicAdd(&g_ce_neg, tot);
    }
}

// ---------------- finalize ----------------
__global__ void final_kernel(float* out) {
    double N = (double)g_total_pos;
    if (N < 1.0) N = 1.0;
    out[0] = (float)(g_loss_l / N);
    out[1] = (float)((g_ce_pos + g_ce_neg) / N);
}

extern "C" void kernel_launch(void* const* d_in, const int* in_sizes, int n_in,
                              void* d_out, int out_size) {
    const float* loc_data  = (const float*)d_in[0];   // [B,P,4]
    const float* conf_data = (const float*)d_in[1];   // [B,P,81]
    const float* priors    = (const float*)d_in[2];   // [P,4]
    const float* targets   = (const float*)d_in[3];   // [B,T,5]
    float* out = (float*)d_out;

    init_kernel<<<1, 1024>>>();
    match_kernel<<<dim3((PP + 255) / 256, BB), 256>>>(priors, targets);
    force_kernel<<<1, BB>>>();
    loss_kernel<<<dim3((PP + 31) / 32, BB), 256>>>(loc_data, conf_data, priors, targets);
    mine_kernel<<<BB, 1024>>>();
    final_kernel<<<1, 1>>>(out);
}

// round 3
// speedup vs baseline: 2.3251x; 1.3581x over previous
#include <cuda_runtime.h>
#include <cstdint>

#define BB 64
#define PP 25000
#define TT 16
#define CC 81
#define ROWS 128      // rows (priors) per loss block
#define NBX ((PP + ROWS - 1) / ROWS)   // 196

// ---------------- scratch ----------------
__device__ float               g_bt_ov[BB * PP];
__device__ unsigned char       g_bt_idx[BB * PP];
__device__ unsigned long long  g_bp_key[BB * TT];
__device__ float               g_loss_c[BB * PP];
__device__ int                 g_num_pos[BB];
__device__ int                 g_total_pos;
__device__ double              g_loss_l;
__device__ double              g_ce_pos;
__device__ double              g_ce_neg;

// ---------------- init ----------------
__global__ void init_kernel() {
    int i = threadIdx.x;
    if (i < BB * TT) g_bp_key[i] = 0ULL;
    if (i < BB)      g_num_pos[i] = 0;
    if (i == 0) { g_total_pos = 0; g_loss_l = 0.0; g_ce_pos = 0.0; g_ce_neg = 0.0; }
}

// ---------------- match ----------------
__global__ void match_kernel(const float* __restrict__ priors,
                             const float* __restrict__ targets) {
    const int b = blockIdx.y;
    const int p = blockIdx.x * 256 + threadIdx.x;
    const int lane = threadIdx.x & 31;
    __shared__ float s_t[TT][4];
    __shared__ float s_ta[TT];
    __shared__ unsigned long long s_key[TT];

    if (threadIdx.x < TT) {
        const float* tr = targets + ((size_t)b * TT + threadIdx.x) * 5;
        float x0 = tr[0], y0 = tr[1], x1 = tr[2], y1 = tr[3];
        s_t[threadIdx.x][0] = x0; s_t[threadIdx.x][1] = y0;
        s_t[threadIdx.x][2] = x1; s_t[threadIdx.x][3] = y1;
        s_ta[threadIdx.x] = (x1 - x0) * (y1 - y0);
        s_key[threadIdx.x] = 0ULL;
    }
    __syncthreads();

    const bool valid = (p < PP);
    float px0 = 0.f, py0 = 0.f, px1 = 0.f, py1 = 0.f, pa = 0.f;
    if (valid) {
        float4 pr = ((const float4*)priors)[p];
        px0 = pr.x - pr.z * 0.5f; py0 = pr.y - pr.w * 0.5f;
        px1 = pr.x + pr.z * 0.5f; py1 = pr.y + pr.w * 0.5f;
        pa  = (px1 - px0) * (py1 - py0);
    }

    float best = -1.0f;
    int   bi   = 0;

    #pragma unroll
    for (int t = 0; t < TT; t++) {
        float iou = -1.0f;
        if (valid) {
            float lx = fmaxf(s_t[t][0], px0), ly = fmaxf(s_t[t][1], py0);
            float rx = fminf(s_t[t][2], px1), ry = fminf(s_t[t][3], py1);
            float iw = fmaxf(rx - lx, 0.0f), ih = fmaxf(ry - ly, 0.0f);
            float inter = iw * ih;
            iou = inter / (s_ta[t] + pa - inter);
            if (iou > best) { best = iou; bi = t; }   // strict > -> first max
        }
        float wmax = iou;
        #pragma unroll
        for (int o = 16; o > 0; o >>= 1)
            wmax = fmaxf(wmax, __shfl_xor_sync(0xffffffffu, wmax, o));
        unsigned ball = __ballot_sync(0xffffffffu, valid && (iou == wmax));
        if (ball != 0 && lane == (__ffs(ball) - 1)) {
            unsigned long long key =
                (((unsigned long long)__float_as_uint(iou)) << 32) | (unsigned)(~(unsigned)p);
            atomicMax(&s_key[t], key);
        }
    }

    if (valid) {
        g_bt_ov[(size_t)b * PP + p]  = best;
        g_bt_idx[(size_t)b * PP + p] = (unsigned char)bi;
    }
    __syncthreads();
    if (threadIdx.x < TT) atomicMax(&g_bp_key[b * TT + threadIdx.x], s_key[threadIdx.x]);
}

// ---------------- force each truth's best prior (last j wins) ----------------
__global__ void force_kernel() {
    int b = threadIdx.x;
    if (b >= BB) return;
    for (int j = 0; j < TT; j++) {
        unsigned long long key = g_bp_key[b * TT + j];
        unsigned p = ~(unsigned)(key & 0xFFFFFFFFULL);
        g_bt_ov[(size_t)b * PP + p]  = 2.0f;
        g_bt_idx[(size_t)b * PP + p] = (unsigned char)j;
    }
}

// ---------------- fused loss: smem-staged, thread-per-row ----------------
__global__ void __launch_bounds__(ROWS) loss_kernel(
        const float* __restrict__ loc_data,
        const float* __restrict__ conf_data,
        const float* __restrict__ priors,
        const float* __restrict__ targets) {
    const int b    = blockIdx.y;
    const int tid  = threadIdx.x;
    const int row0 = blockIdx.x * ROWS;
    const int n    = min(ROWS, PP - row0);     // 128 or 40 (both *81 divisible by 4)

    __shared__ float s_conf[ROWS * CC];        // 41472 B
    __shared__ float s_tr[TT][5];
    __shared__ float s_ll[4], s_cep[4];
    __shared__ int   s_pos[4];

    if (tid < TT * 5)
        ((float*)s_tr)[tid] = targets[(size_t)b * TT * 5 + tid];

    // ---- stage conf tile: contiguous, 16B-aligned, coalesced float4 ----
    {
        const float4* g4 = (const float4*)(conf_data + ((size_t)b * PP + row0) * CC);
        float4* s4 = (float4*)s_conf;
        const int nf4 = (n * CC) >> 2;         // 2592 or 810
        #pragma unroll 4
        for (int i = tid; i < nf4; i += ROWS)
            s4[i] = __ldcs(g4 + i);
    }
    __syncthreads();

    float my_ll = 0.f, my_cep = 0.f;
    int   my_pos = 0;

    if (tid < n) {
        const int p = row0 + tid;
        const float* rowp = s_conf + tid * CC; // bank stride 17 -> conflict-free

        float sum = 0.f;
        #pragma unroll
        for (int i = 0; i < CC; i++) sum += __expf(rowp[i]);
        float lse = __logf(sum);

        float ov = g_bt_ov[(size_t)b * PP + p];
        int   ti = g_bt_idx[(size_t)b * PP + p];
        bool pos = (ov >= 0.5f);
        int  ct  = pos ? ((int)s_tr[ti][4] + 1) : 0;
        float ce = lse - rowp[ct];

        g_loss_c[(size_t)b * PP + p] = pos ? 0.f : ce;

        if (pos) {
            my_pos = 1;
            my_cep = ce;
            float4 pr = ((const float4*)priors)[p];
            float tx0 = s_tr[ti][0], ty0 = s_tr[ti][1];
            float tx1 = s_tr[ti][2], ty1 = s_tr[ti][3];
            float gx = ((tx0 + tx1) * 0.5f - pr.x) / (0.1f * pr.z);
            float gy = ((ty0 + ty1) * 0.5f - pr.y) / (0.1f * pr.w);
            float gw = __logf((tx1 - tx0) / pr.z) * 5.0f;
            float gh = __logf((ty1 - ty0) / pr.w) * 5.0f;
            float4 ld = ((const float4*)loc_data)[(size_t)b * PP + p];
            float d, ad;
            d = ld.x - gx; ad = fabsf(d); my_ll += (ad < 1.f) ? 0.5f * d * d : ad - 0.5f;
            d = ld.y - gy; ad = fabsf(d); my_ll += (ad < 1.f) ? 0.5f * d * d : ad - 0.5f;
            d = ld.z - gw; ad = fabsf(d); my_ll += (ad < 1.f) ? 0.5f * d * d : ad - 0.5f;
            d = ld.w - gh; ad = fabsf(d); my_ll += (ad < 1.f) ? 0.5f * d * d : ad - 0.5f;
        }
    }

    // ---- block reduce (4 warps) ----
    #pragma unroll
    for (int o = 16; o > 0; o >>= 1) {
        my_ll  += __shfl_xor_sync(0xffffffffu, my_ll, o);
        my_cep += __shfl_xor_sync(0xffffffffu, my_cep, o);
        my_pos += __shfl_xor_sync(0xffffffffu, my_pos, o);
    }
    const int lane = tid & 31, warp = tid >> 5;
    if (lane == 0) { s_ll[warp] = my_ll; s_cep[warp] = my_cep; s_pos[warp] = my_pos; }
    __syncthreads();
    if (tid == 0) {
        float ll = s_ll[0] + s_ll[1] + s_ll[2] + s_ll[3];
        float cep = s_cep[0] + s_cep[1] + s_cep[2] + s_cep[3];
        int   np = s_pos[0] + s_pos[1] + s_pos[2] + s_pos[3];
        if (np) {
            atomicAdd(&g_loss_l, (double)ll);
            atomicAdd(&g_ce_pos, (double)cep);
            atomicAdd(&g_num_pos[b], np);
            atomicAdd(&g_total_pos, np);
        }
    }
}

// ---------------- hard-negative mining: 3-pass radix select + sum ----------------
__global__ void mine_kernel() {
    const int b   = blockIdx.x;
    const int tid = threadIdx.x;
    __shared__ int      hist[2048];
    __shared__ int      s_group[64];
    __shared__ unsigned s_prefix;
    __shared__ int      s_kk;

    int np = g_num_pos[b];
    int k  = min(3 * np, PP - 1);
    if (k <= 0) return;  // uniform across block

    const float* lc = g_loss_c + (size_t)b * PP;
    unsigned prefix = 0;
    int kk = k;

    const int shifts[3] = {21, 10, 0};
    const int nbits [3] = {11, 11, 10};

    #pragma unroll
    for (int pass = 0; pass < 3; pass++) {
        const int shift = shifts[pass];
        const int nb    = 1 << nbits[pass];
        hist[tid] = 0; hist[tid + 1024] = 0;
        __syncthreads();
        const unsigned hmask = (pass == 0) ? 0u : (0xFFFFFFFFu << (shift + nbits[pass]));
        const unsigned bmask = (unsigned)(nb - 1);

        int i = tid;
        for (; i + 3 * 1024 < PP; i += 4 * 1024) {
            unsigned k0 = __float_as_uint(lc[i]);
            unsigned k1 = __float_as_uint(lc[i + 1024]);
            unsigned k2 = __float_as_uint(lc[i + 2048]);
            unsigned k3 = __float_as_uint(lc[i + 3072]);
            if ((k0 & hmask) == prefix) atomicAdd(&hist[(k0 >> shift) & bmask], 1);
            if ((k1 & hmask) == prefix) atomicAdd(&hist[(k1 >> shift) & bmask], 1);
            if ((k2 & hmask) == prefix) atomicAdd(&hist[(k2 >> shift) & bmask], 1);
            if ((k3 & hmask) == prefix) atomicAdd(&hist[(k3 >> shift) & bmask], 1);
        }
        for (; i < PP; i += 1024) {
            unsigned key = __float_as_uint(lc[i]);
            if ((key & hmask) == prefix) atomicAdd(&hist[(key >> shift) & bmask], 1);
        }
        __syncthreads();

        const int ngroups = nb >> 5;
        if (tid < ngroups) {
            int s = 0;
            #pragma unroll
            for (int j = 0; j < 32; j++) s += hist[tid * 32 + j];
            s_group[tid] = s;
        }
        __syncthreads();
        if (tid == 0) {
            int cum = 0, g = ngroups - 1;
            for (; g > 0; g--) {
                if (cum + s_group[g] >= kk) break;
                cum += s_group[g];
            }
            int x = g * 32 + 31;
            for (;; x--) {
                int h = hist[x];
                if (cum + h >= kk || x == g * 32) break;
                cum += h;
            }
            s_prefix = prefix | ((unsigned)x << shift);
            s_kk = kk - cum;
        }
        __syncthreads();
        prefix = s_prefix;
        kk     = s_kk;
    }

    float  thr   = __uint_as_float(prefix);
    double local = 0.0;
    {
        int i = tid;
        for (; i + 3 * 1024 < PP; i += 4 * 1024) {
            float a0 = lc[i], a1 = lc[i + 1024], a2 = lc[i + 2048], a3 = lc[i + 3072];
            if (__float_as_uint(a0) > prefix) local += (double)a0;
            if (__float_as_uint(a1) > prefix) local += (double)a1;
            if (__float_as_uint(a2) > prefix) local += (double)a2;
            if (__float_as_uint(a3) > prefix) local += (double)a3;
        }
        for (; i < PP; i += 1024) {
            float v = lc[i];
            if (__float_as_uint(v) > prefix) local += (double)v;
        }
    }
    #pragma unroll
    for (int o = 16; o > 0; o >>= 1) local += __shfl_xor_sync(0xffffffffu, local, o);
    __shared__ double sdl[32];
    int lane = tid & 31, w = tid >> 5;
    if (lane == 0) sdl[w] = local;
    __syncthreads();
    if (tid == 0) {
        double tot = 0.0;
        for (int i = 0; i < 32; i++) tot += sdl[i];
        tot += (double)kk * (double)thr;
        atomicAdd(&g_ce_neg, tot);
    }
}

// ---------------- finalize ----------------
__global__ void final_kernel(float* out) {
    double N = (double)g_total_pos;
    if (N < 1.0) N = 1.0;
    out[0] = (float)(g_loss_l / N);
    out[1] = (float)((g_ce_pos + g_ce_neg) / N);
}

extern "C" void kernel_launch(void* const* d_in, const int* in_sizes, int n_in,
                              void* d_out, int out_size) {
    const float* loc_data  = (const float*)d_in[0];   // [B,P,4]
    const float* conf_data = (const float*)d_in[1];   // [B,P,81]
    const float* priors    = (const float*)d_in[2];   // [P,4]
    const float* targets   = (const float*)d_in[3];   // [B,T,5]
    float* out = (float*)d_out;

    init_kernel<<<1, 1024>>>();
    match_kernel<<<dim3((PP + 255) / 256, BB), 256>>>(priors, targets);
    force_kernel<<<1, BB>>>();
    loss_kernel<<<dim3(NBX, BB), ROWS>>>(loc_data, conf_data, priors, targets);
    mine_kernel<<<BB, 1024>>>();
    final_kernel<<<1, 1>>>(out);
}

// round 5
// speedup vs baseline: 2.4623x; 1.0590x over previous
#include <cuda_runtime.h>
#include <cstdint>

#define BB 64
#define PP 25000
#define TT 16
#define CC 81

#define LROWS 64                         // rows per pipeline stage
#define LTILES 4                         // stages per block
#define NTILE ((PP + LROWS - 1) / LROWS) // 391
#define LNBX ((NTILE + LTILES - 1) / LTILES) // 98

// ---------------- scratch ----------------
__device__ float               g_bt_ov[BB * PP];
__device__ unsigned char       g_bt_idx[BB * PP];
__device__ unsigned long long  g_bp_key[BB * TT];
__device__ float               g_loss_c[BB * PP];
__device__ int                 g_num_pos[BB];
__device__ int                 g_total_pos;
__device__ double              g_loss_l;
__device__ double              g_ce_pos;
__device__ double              g_ce_neg;

// ---------------- cp.async helpers ----------------
__device__ __forceinline__ void cp_async16(void* smem, const void* gmem) {
    unsigned saddr = (unsigned)__cvta_generic_to_shared(smem);
    asm volatile("cp.async.cg.shared.global [%0], [%1], 16;" :: "r"(saddr), "l"(gmem));
}
__device__ __forceinline__ void cp_commit() {
    asm volatile("cp.async.commit_group;");
}
template <int N>
__device__ __forceinline__ void cp_wait() {
    asm volatile("cp.async.wait_group %0;" :: "n"(N));
}

// ---------------- init ----------------
__global__ void init_kernel() {
    int i = threadIdx.x;
    if (i < BB * TT) g_bp_key[i] = 0ULL;
    if (i < BB)      g_num_pos[i] = 0;
    if (i == 0) { g_total_pos = 0; g_loss_l = 0.0; g_ce_pos = 0.0; g_ce_neg = 0.0; }
}

// ---------------- match ----------------
__global__ void match_kernel(const float* __restrict__ priors,
                             const float* __restrict__ targets) {
    const int b = blockIdx.y;
    const int p = blockIdx.x * 256 + threadIdx.x;
    const int lane = threadIdx.x & 31;
    __shared__ float s_t[TT][4];
    __shared__ float s_ta[TT];
    __shared__ unsigned long long s_key[TT];

    if (threadIdx.x < TT) {
        const float* tr = targets + ((size_t)b * TT + threadIdx.x) * 5;
        float x0 = tr[0], y0 = tr[1], x1 = tr[2], y1 = tr[3];
        s_t[threadIdx.x][0] = x0; s_t[threadIdx.x][1] = y0;
        s_t[threadIdx.x][2] = x1; s_t[threadIdx.x][3] = y1;
        s_ta[threadIdx.x] = (x1 - x0) * (y1 - y0);
        s_key[threadIdx.x] = 0ULL;
    }
    __syncthreads();

    const bool valid = (p < PP);
    float px0 = 0.f, py0 = 0.f, px1 = 0.f, py1 = 0.f, pa = 0.f;
    if (valid) {
        float4 pr = ((const float4*)priors)[p];
        px0 = pr.x - pr.z * 0.5f; py0 = pr.y - pr.w * 0.5f;
        px1 = pr.x + pr.z * 0.5f; py1 = pr.y + pr.w * 0.5f;
        pa  = (px1 - px0) * (py1 - py0);
    }

    float best = -1.0f;
    int   bi   = 0;

    #pragma unroll
    for (int t = 0; t < TT; t++) {
        unsigned ib = 0;
        if (valid) {
            float lx = fmaxf(s_t[t][0], px0), ly = fmaxf(s_t[t][1], py0);
            float rx = fminf(s_t[t][2], px1), ry = fminf(s_t[t][3], py1);
            float iw = fmaxf(rx - lx, 0.0f), ih = fmaxf(ry - ly, 0.0f);
            float inter = iw * ih;
            float iou = inter / (s_ta[t] + pa - inter);
            if (iou > best) { best = iou; bi = t; }   // strict > -> first max
            ib = __float_as_uint(iou);                // iou >= 0 -> order-preserving
        }
        unsigned wmax = __reduce_max_sync(0xffffffffu, ib);   // single REDUX, all lanes
        unsigned ball = __ballot_sync(0xffffffffu, valid && (ib == wmax));
        if (ball != 0 && lane == (__ffs(ball) - 1)) {
            unsigned long long key =
                (((unsigned long long)wmax) << 32) | (unsigned)(~(unsigned)p);
            atomicMax(&s_key[t], key);
        }
    }

    if (valid) {
        g_bt_ov[(size_t)b * PP + p]  = best;
        g_bt_idx[(size_t)b * PP + p] = (unsigned char)bi;
    }
    __syncthreads();
    if (threadIdx.x < TT) atomicMax(&g_bp_key[b * TT + threadIdx.x], s_key[threadIdx.x]);
}

// ---------------- force each truth's best prior (last j wins) ----------------
__global__ void force_kernel() {
    int b = threadIdx.x;
    if (b >= BB) return;
    for (int j = 0; j < TT; j++) {
        unsigned long long key = g_bp_key[b * TT + j];
        unsigned p = ~(unsigned)(key & 0xFFFFFFFFULL);
        g_bt_ov[(size_t)b * PP + p]  = 2.0f;
        g_bt_idx[(size_t)b * PP + p] = (unsigned char)j;
    }
}

// ---------------- fused loss: double-buffered cp.async, 2 threads/row ----------------
__global__ void __launch_bounds__(128) loss_kernel(
        const float* __restrict__ loc_data,
        const float* __restrict__ conf_data,
        const float* __restrict__ priors,
        const float* __restrict__ targets) {
    const int b    = blockIdx.y;
    const int tid  = threadIdx.x;
    const int t0   = blockIdx.x * LTILES;            // first tile index
    const int S    = min(LTILES, NTILE - t0);        // stages this block

    __shared__ float s_buf[2][LROWS * CC];           // 2 x 20736 B
    __shared__ float s_tr[TT][5];
    __shared__ float s_ll[4], s_cep[4];
    __shared__ int   s_pos[4];

    if (tid < TT * 5)
        ((float*)s_tr)[tid] = targets[(size_t)b * TT * 5 + tid];

    const float* cbase = conf_data + (size_t)b * PP * CC;

    // prefetch stage 0
    {
        const int row0 = t0 * LROWS;
        const int nf4  = (min(LROWS, PP - row0) * CC) >> 2;
        const float4* g4 = (const float4*)(cbase + (size_t)row0 * CC);
        float4* s4 = (float4*)s_buf[0];
        for (int i = tid; i < nf4; i += 128) cp_async16(s4 + i, g4 + i);
        cp_commit();
    }

    float my_ll = 0.f, my_cep = 0.f;
    int   my_pos = 0;

    const int r    = tid >> 1;       // row within tile
    const int half = tid & 1;        // 0: [0,40) ; 1: [40,81)

    for (int s = 0; s < S; s++) {
        if (s + 1 < S) {
            const int row0 = (t0 + s + 1) * LROWS;
            const int nf4  = (min(LROWS, PP - row0) * CC) >> 2;
            const float4* g4 = (const float4*)(cbase + (size_t)row0 * CC);
            float4* s4 = (float4*)s_buf[(s + 1) & 1];
            for (int i = tid; i < nf4; i += 128) cp_async16(s4 + i, g4 + i);
            cp_commit();
            cp_wait<1>();
        } else {
            cp_wait<0>();
        }
        __syncthreads();

        const int row0 = (t0 + s) * LROWS;
        const int n    = min(LROWS, PP - row0);
        const float* rowp = s_buf[s & 1] + r * CC;
        const bool   act  = (r < n);

        // sum half-row (garbage smem for inactive rows is harmless; discarded)
        float sum = 0.f;
        if (act) {
            if (half == 0) {
                #pragma unroll
                for (int i = 0; i < 40; i++) sum += __expf(rowp[i]);
            } else {
                #pragma unroll
                for (int i = 40; i < CC; i++) sum += __expf(rowp[i]);
            }
        }
        // UNCONDITIONAL warp-uniform shuffle (R4 hang fix)
        float tot = sum + __shfl_xor_sync(0xffffffffu, sum, 1);

        if (act && half == 0) {
            const int p = row0 + r;
            float lse = __logf(tot);
            float ov = g_bt_ov[(size_t)b * PP + p];
            int   ti = g_bt_idx[(size_t)b * PP + p];
            bool pos = (ov >= 0.5f);
            int  ct  = pos ? ((int)s_tr[ti][4] + 1) : 0;
            float ce = lse - rowp[ct];
            g_loss_c[(size_t)b * PP + p] = pos ? 0.f : ce;
            if (pos) {
                my_pos++;
                my_cep += ce;
                float4 pr = ((const float4*)priors)[p];
                float tx0 = s_tr[ti][0], ty0 = s_tr[ti][1];
                float tx1 = s_tr[ti][2], ty1 = s_tr[ti][3];
                float gx = ((tx0 + tx1) * 0.5f - pr.x) / (0.1f * pr.z);
                float gy = ((ty0 + ty1) * 0.5f - pr.y) / (0.1f * pr.w);
                float gw = __logf((tx1 - tx0) / pr.z) * 5.0f;
                float gh = __logf((ty1 - ty0) / pr.w) * 5.0f;
                float4 ld = ((const float4*)loc_data)[(size_t)b * PP + p];
                float d, ad;
                d = ld.x - gx; ad = fabsf(d); my_ll += (ad < 1.f) ? 0.5f * d * d : ad - 0.5f;
                d = ld.y - gy; ad = fabsf(d); my_ll += (ad < 1.f) ? 0.5f * d * d : ad - 0.5f;
                d = ld.z - gw; ad = fabsf(d); my_ll += (ad < 1.f) ? 0.5f * d * d : ad - 0.5f;
                d = ld.w - gh; ad = fabsf(d); my_ll += (ad < 1.f) ? 0.5f * d * d : ad - 0.5f;
            }
        }
        __syncthreads();   // buffer (s&1) safe to refill at iteration s+1's prefetch
    }

    // ---- block reduce (all threads participate) ----
    #pragma unroll
    for (int o = 16; o > 0; o >>= 1) {
        my_ll  += __shfl_xor_sync(0xffffffffu, my_ll, o);
        my_cep += __shfl_xor_sync(0xffffffffu, my_cep, o);
        my_pos += __shfl_xor_sync(0xffffffffu, my_pos, o);
    }
    const int lane = tid & 31, warp = tid >> 5;
    if (lane == 0) { s_ll[warp] = my_ll; s_cep[warp] = my_cep; s_pos[warp] = my_pos; }
    __syncthreads();
    if (tid == 0) {
        float ll = s_ll[0] + s_ll[1] + s_ll[2] + s_ll[3];
        float cep = s_cep[0] + s_cep[1] + s_cep[2] + s_cep[3];
        int   np = s_pos[0] + s_pos[1] + s_pos[2] + s_pos[3];
        if (np) {
            atomicAdd(&g_loss_l, (double)ll);
            atomicAdd(&g_ce_pos, (double)cep);
            atomicAdd(&g_num_pos[b], np);
            atomicAdd(&g_total_pos, np);
        }
    }
}

// ---------------- hard-negative mining: 3-pass radix select + sum ----------------
__global__ void mine_kernel() {
    const int b   = blockIdx.x;
    const int tid = threadIdx.x;
    __shared__ int      hist[2048];
    __shared__ int      s_group[64];
    __shared__ unsigned s_prefix;
    __shared__ int      s_kk;

    int np = g_num_pos[b];
    int k  = min(3 * np, PP - 1);
    if (k <= 0) return;  // uniform across block

    const float* lc = g_loss_c + (size_t)b * PP;
    unsigned prefix = 0;
    int kk = k;

    const int shifts[3] = {21, 10, 0};
    const int nbits [3] = {11, 11, 10};

    #pragma unroll
    for (int pass = 0; pass < 3; pass++) {
        const int shift = shifts[pass];
        const int nb    = 1 << nbits[pass];
        hist[tid] = 0; hist[tid + 1024] = 0;
        __syncthreads();
        const unsigned hmask = (pass == 0) ? 0u : (0xFFFFFFFFu << (shift + nbits[pass]));
        const unsigned bmask = (unsigned)(nb - 1);

        int i = tid;
        for (; i + 7 * 1024 < PP; i += 8 * 1024) {
            unsigned kx[8];
            #pragma unroll
            for (int u = 0; u < 8; u++) kx[u] = __float_as_uint(lc[i + u * 1024]);
            #pragma unroll
            for (int u = 0; u < 8; u++)
                if ((kx[u] & hmask) == prefix) atomicAdd(&hist[(kx[u] >> shift) & bmask], 1);
        }
        for (; i < PP; i += 1024) {
            unsigned key = __float_as_uint(lc[i]);
            if ((key & hmask) == prefix) atomicAdd(&hist[(key >> shift) & bmask], 1);
        }
        __syncthreads();

        const int ngroups = nb >> 5;
        if (tid < ngroups) {
            int s = 0;
            #pragma unroll
            for (int j = 0; j < 32; j++) s += hist[tid * 32 + j];
            s_group[tid] = s;
        }
        __syncthreads();
        if (tid == 0) {
            int cum = 0, g = ngroups - 1;
            for (; g > 0; g--) {
                if (cum + s_group[g] >= kk) break;
                cum += s_group[g];
            }
            int x = g * 32 + 31;
            for (;; x--) {
                int h = hist[x];
                if (cum + h >= kk || x == g * 32) break;
                cum += h;
            }
            s_prefix = prefix | ((unsigned)x << shift);
            s_kk = kk - cum;
        }
        __syncthreads();
        prefix = s_prefix;
        kk     = s_kk;
    }

    float  thr   = __uint_as_float(prefix);
    double local = 0.0;
    {
        int i = tid;
        for (; i + 7 * 1024 < PP; i += 8 * 1024) {
            float a[8];
            #pragma unroll
            for (int u = 0; u < 8; u++) a[u] = lc[i + u * 1024];
            #pragma unroll
            for (int u = 0; u < 8; u++)
                if (__float_as_uint(a[u]) > prefix) local += (double)a[u];
        }
        for (; i < PP; i += 1024) {
            float v = lc[i];
            if (__float_as_uint(v) > prefix) local += (double)v;
        }
    }
    #pragma unroll
    for (int o = 16; o > 0; o >>= 1) local += __shfl_xor_sync(0xffffffffu, local, o);
    __shared__ double sdl[32];
    int lane = tid & 31, w = tid >> 5;
    if (lane == 0) sdl[w] = local;
    __syncthreads();
    if (tid == 0) {
        double tot = 0.0;
        for (int i = 0; i < 32; i++) tot += sdl[i];
        tot += (double)kk * (double)thr;
        atomicAdd(&g_ce_neg, tot);
    }
}

// ---------------- finalize ----------------
__global__ void final_kernel(float* out) {
    double N = (double)g_total_pos;
    if (N < 1.0) N = 1.0;
    out[0] = (float)(g_loss_l / N);
    out[1] = (float)((g_ce_pos + g_ce_neg) / N);
}

extern "C" void kernel_launch(void* const* d_in, const int* in_sizes, int n_in,
                              void* d_out, int out_size) {
    const float* loc_data  = (const float*)d_in[0];   // [B,P,4]
    const float* conf_data = (const float*)d_in[1];   // [B,P,81]
    const float* priors    = (const float*)d_in[2];   // [P,4]
    const float* targets   = (const float*)d_in[3];   // [B,T,5]
    float* out = (float*)d_out;

    init_kernel<<<1, 1024>>>();
    match_kernel<<<dim3((PP + 255) / 256, BB), 256>>>(priors, targets);
    force_kernel<<<1, BB>>>();
    loss_kernel<<<dim3(LNBX, BB), 128>>>(loc_data, conf_data, priors, targets);
    mine_kernel<<<BB, 1024>>>();
    final_kernel<<<1, 1>>>(out);
}

// round 7
// speedup vs baseline: 2.4861x; 1.0096x over previous
#include <cuda_runtime.h>
#include <cstdint>

#define BB 64
#define PP 25000
#define TT 16
#define CC 81

#define LROWS 64
#define LTILES 8
#define NTILE ((PP + LROWS - 1) / LROWS)          // 391
#define LNBX ((NTILE + LTILES - 1) / LTILES)      // 49

// ---------------- scratch ----------------
__device__ float               g_bt_ov[BB * PP];
__device__ unsigned char       g_bt_idx[BB * PP];
__device__ unsigned long long  g_bp_key[BB * TT];
__device__ float               g_loss_c[BB * PP];
__device__ int                 g_hist1[BB * 2048];    // top-11-bit histogram per batch
__device__ int                 g_num_pos[BB];
__device__ int                 g_total_pos;
__device__ double              g_loss_l;
__device__ double              g_ce_pos;
__device__ double              g_ce_neg;

// ---------------- cp.async helpers ----------------
__device__ __forceinline__ void cp_async16(void* smem, const void* gmem) {
    unsigned saddr = (unsigned)__cvta_generic_to_shared(smem);
    asm volatile("cp.async.cg.shared.global [%0], [%1], 16;" :: "r"(saddr), "l"(gmem));
}
__device__ __forceinline__ void cp_commit() {
    asm volatile("cp.async.commit_group;");
}
template <int N>
__device__ __forceinline__ void cp_wait() {
    asm volatile("cp.async.wait_group %0;" :: "n"(N));
}

// ---------------- init: one block per batch zeroes its histogram ----------------
__global__ void init_kernel() {
    int b = blockIdx.x, tid = threadIdx.x;
    g_hist1[b * 2048 + tid] = 0;
    g_hist1[b * 2048 + 1024 + tid] = 0;
    if (b == 0) {
        g_bp_key[tid] = 0ULL;                      // BB*TT == 1024
        if (tid < BB) g_num_pos[tid] = 0;
        if (tid == 0) { g_total_pos = 0; g_loss_l = 0.0; g_ce_pos = 0.0; g_ce_neg = 0.0; }
    }
}

// ---------------- match ----------------
__global__ void match_kernel(const float* __restrict__ priors,
                             const float* __restrict__ targets) {
    const int b = blockIdx.y;
    const int p = blockIdx.x * 256 + threadIdx.x;
    const int lane = threadIdx.x & 31;
    __shared__ float s_t[TT][4];
    __shared__ float s_ta[TT];
    __shared__ unsigned long long s_key[TT];

    if (threadIdx.x < TT) {
        const float* tr = targets + ((size_t)b * TT + threadIdx.x) * 5;
        float x0 = tr[0], y0 = tr[1], x1 = tr[2], y1 = tr[3];
        s_t[threadIdx.x][0] = x0; s_t[threadIdx.x][1] = y0;
        s_t[threadIdx.x][2] = x1; s_t[threadIdx.x][3] = y1;
        s_ta[threadIdx.x] = (x1 - x0) * (y1 - y0);
        s_key[threadIdx.x] = 0ULL;
    }
    __syncthreads();

    const bool valid = (p < PP);
    float px0 = 0.f, py0 = 0.f, px1 = 0.f, py1 = 0.f, pa = 0.f;
    if (valid) {
        float4 pr = ((const float4*)priors)[p];
        px0 = pr.x - pr.z * 0.5f; py0 = pr.y - pr.w * 0.5f;
        px1 = pr.x + pr.z * 0.5f; py1 = pr.y + pr.w * 0.5f;
        pa  = (px1 - px0) * (py1 - py0);
    }

    float best = -1.0f;
    int   bi   = 0;

    #pragma unroll
    for (int t = 0; t < TT; t++) {
        unsigned ib = 0;
        if (valid) {
            float lx = fmaxf(s_t[t][0], px0), ly = fmaxf(s_t[t][1], py0);
            float rx = fminf(s_t[t][2], px1), ry = fminf(s_t[t][3], py1);
            float iw = fmaxf(rx - lx, 0.0f), ih = fmaxf(ry - ly, 0.0f);
            float inter = iw * ih;
            float iou = inter / (s_ta[t] + pa - inter);
            if (iou > best) { best = iou; bi = t; }           // strict > -> first max
            ib = __float_as_uint(iou);                        // iou >= 0 -> order-preserving
        }
        unsigned wmax = __reduce_max_sync(0xffffffffu, ib);
        unsigned cp   = (valid && ib == wmax) ? (unsigned)p : 0xFFFFFFFFu;
        unsigned pmin = __reduce_min_sync(0xffffffffu, cp);
        if (lane == 0) {
            unsigned long long key = (((unsigned long long)wmax) << 32) | (unsigned)(~pmin);
            atomicMax(&s_key[t], key);
        }
    }

    if (valid) {
        g_bt_ov[(size_t)b * PP + p]  = best;
        g_bt_idx[(size_t)b * PP + p] = (unsigned char)bi;
    }
    __syncthreads();
    if (threadIdx.x < TT) atomicMax(&g_bp_key[b * TT + threadIdx.x], s_key[threadIdx.x]);
}

// ---------------- force each truth's best prior (last j wins) ----------------
__global__ void force_kernel() {
    int b = threadIdx.x;
    if (b >= BB) return;
    for (int j = 0; j < TT; j++) {
        unsigned long long key = g_bp_key[b * TT + j];
        unsigned p = ~(unsigned)(key & 0xFFFFFFFFULL);
        g_bt_ov[(size_t)b * PP + p]  = 2.0f;
        g_bt_idx[(size_t)b * PP + p] = (unsigned char)j;
    }
}

// ---------------- fused loss: cp.async pipeline + strip-vectorized exp sum ----------------
// 4-row strips (324 floats, 16B aligned); 8 threads/strip; thread h: floats [40h, 40h+40)
// (h7 gets 44). <=1 row boundary per thread -> two partials, combined in smem.
__global__ void __launch_bounds__(128) loss_kernel(
        const float* __restrict__ loc_data,
        const float* __restrict__ conf_data,
        const float* __restrict__ priors,
        const float* __restrict__ targets) {
    const int b   = blockIdx.y;
    const int tid = threadIdx.x;
    const int t0  = blockIdx.x * LTILES;
    const int S   = min(LTILES, NTILE - t0);

    __shared__ float s_buf[2][LROWS * CC];        // 2 x 20736 B
    __shared__ float s_pa[128], s_pb[128];
    __shared__ float s_tr[TT][5];
    __shared__ float s_ll[4], s_cep[4];
    __shared__ int   s_pos[4];

    if (tid < TT * 5)
        ((float*)s_tr)[tid] = targets[(size_t)b * TT * 5 + tid];

    const float* cbase = conf_data + (size_t)b * PP * CC;

    // prefetch stage 0
    {
        const int row0 = t0 * LROWS;
        const int nf4  = (min(LROWS, PP - row0) * CC) >> 2;
        const float4* g4 = (const float4*)(cbase + (size_t)row0 * CC);
        float4* s4 = (float4*)s_buf[0];
        for (int i = tid; i < nf4; i += 128) cp_async16(s4 + i, g4 + i);
        cp_commit();
    }

    float my_ll = 0.f, my_cep = 0.f;
    int   my_pos = 0;

    const int st  = tid >> 3;                 // strip 0..15
    const int h   = tid & 7;
    const int fs  = 40 * h;                   // first float in strip
    const int nf  = (h == 7) ? 11 : 10;       // float4 count
    const int fe  = fs + 4 * nf;
    const int rAx = fs / 81;                  // row of first float: {0,0,0,1,1,2,2,3} (R6 bug fix)
    const int splitf = min((rAx + 1) * 81, fe);

    for (int s = 0; s < S; s++) {
        if (s + 1 < S) {
            const int row0 = (t0 + s + 1) * LROWS;
            const int nf4  = (min(LROWS, PP - row0) * CC) >> 2;
            const float4* g4 = (const float4*)(cbase + (size_t)row0 * CC);
            float4* s4 = (float4*)s_buf[(s + 1) & 1];
            for (int i = tid; i < nf4; i += 128) cp_async16(s4 + i, g4 + i);
            cp_commit();
            cp_wait<1>();
        } else {
            cp_wait<0>();
        }
        __syncthreads();

        const int row0 = (t0 + s) * LROWS;
        const int n    = min(LROWS, PP - row0);
        const float* base = s_buf[s & 1];

        float accA = 0.f, accB = 0.f;
        if (st * 4 < n) {
            const float* tp = base + st * 324 + fs;
            #pragma unroll
            for (int i = 0; i < 11; i++) {
                if (i < nf) {
                    float4 v = *(const float4*)(tp + 4 * i);
                    float e0 = __expf(v.x), e1 = __expf(v.y);
                    float e2 = __expf(v.z), e3 = __expf(v.w);
                    float sv = (e0 + e1) + (e2 + e3);
                    int w = fs + 4 * i;
                    if (w + 4 <= splitf)      accA += sv;
                    else if (w >= splitf)     accB += sv;
                    else {
                        accA += (w     < splitf ? e0 : 0.f) + (w + 1 < splitf ? e1 : 0.f)
                              + (w + 2 < splitf ? e2 : 0.f) + (w + 3 < splitf ? e3 : 0.f);
                        accB += (w     >= splitf ? e0 : 0.f) + (w + 1 >= splitf ? e1 : 0.f)
                              + (w + 2 >= splitf ? e2 : 0.f) + (w + 3 >= splitf ? e3 : 0.f);
                    }
                }
            }
        }
        s_pa[tid] = accA; s_pb[tid] = accB;
        __syncthreads();

        if (tid < n) {
            const int ss = tid >> 2, r = tid & 3;
            const float* pa = s_pa + ss * 8;
            const float* pb = s_pb + ss * 8;
            float tot = (r == 0) ? pa[0] + pa[1] + pa[2]
                      : (r == 1) ? pb[2] + pa[3] + pa[4]
                      : (r == 2) ? pb[4] + pa[5] + pa[6]
                      :            pb[6] + pa[7];
            const int p = row0 + tid;
            float lse = __logf(tot);
            float ov = g_bt_ov[(size_t)b * PP + p];
            int   ti = g_bt_idx[(size_t)b * PP + p];
            bool pos = (ov >= 0.5f);
            int  ct  = pos ? ((int)s_tr[ti][4] + 1) : 0;
            float ce = lse - base[ss * 324 + r * 81 + ct];
            float lc = pos ? 0.f : ce;
            g_loss_c[(size_t)b * PP + p] = lc;
            atomicAdd(&g_hist1[b * 2048 + (int)(__float_as_uint(lc) >> 21)], 1);
            if (pos) {
                my_pos++;
                my_cep += ce;
                float4 pr = ((const float4*)priors)[p];
                float tx0 = s_tr[ti][0], ty0 = s_tr[ti][1];
                float tx1 = s_tr[ti][2], ty1 = s_tr[ti][3];
                float gx = ((tx0 + tx1) * 0.5f - pr.x) / (0.1f * pr.z);
                float gy = ((ty0 + ty1) * 0.5f - pr.y) / (0.1f * pr.w);
                float gw = __logf((tx1 - tx0) / pr.z) * 5.0f;
                float gh = __logf((ty1 - ty0) / pr.w) * 5.0f;
                float4 ld = ((const float4*)loc_data)[(size_t)b * PP + p];
                float d, ad;
                d = ld.x - gx; ad = fabsf(d); my_ll += (ad < 1.f) ? 0.5f * d * d : ad - 0.5f;
                d = ld.y - gy; ad = fabsf(d); my_ll += (ad < 1.f) ? 0.5f * d * d : ad - 0.5f;
                d = ld.z - gw; ad = fabsf(d); my_ll += (ad < 1.f) ? 0.5f * d * d : ad - 0.5f;
                d = ld.w - gh; ad = fabsf(d); my_ll += (ad < 1.f) ? 0.5f * d * d : ad - 0.5f;
            }
        }
        __syncthreads();
    }

    // ---- block reduce ----
    #pragma unroll
    for (int o = 16; o > 0; o >>= 1) {
        my_ll  += __shfl_xor_sync(0xffffffffu, my_ll, o);
        my_cep += __shfl_xor_sync(0xffffffffu, my_cep, o);
        my_pos += __shfl_xor_sync(0xffffffffu, my_pos, o);
    }
    const int lane = tid & 31, warp = tid >> 5;
    if (lane == 0) { s_ll[warp] = my_ll; s_cep[warp] = my_cep; s_pos[warp] = my_pos; }
    __syncthreads();
    if (tid == 0) {
        float ll = s_ll[0] + s_ll[1] + s_ll[2] + s_ll[3];
        float cep = s_cep[0] + s_cep[1] + s_cep[2] + s_cep[3];
        int   np = s_pos[0] + s_pos[1] + s_pos[2] + s_pos[3];
        if (np) {
            atomicAdd(&g_loss_l, (double)ll);
            atomicAdd(&g_ce_pos, (double)cep);
            atomicAdd(&g_num_pos[b], np);
            atomicAdd(&g_total_pos, np);
        }
    }
}

// ---------------- mining: pass1 from precomputed hist, then 2 radix sweeps ----------------
__global__ void mine_kernel() {
    const int b   = blockIdx.x;
    const int tid = threadIdx.x;
    __shared__ int      hist[2048];
    __shared__ int      s_group[64];
    __shared__ unsigned s_prefix;
    __shared__ int      s_kk;

    int np = g_num_pos[b];
    int k  = min(3 * np, PP - 1);
    if (k <= 0) return;  // uniform across block

    const float* lc = g_loss_c + (size_t)b * PP;
    unsigned prefix = 0;
    int kk = k;

    // ---- pass 1: use precomputed histogram (bits 31..21) ----
    hist[tid] = g_hist1[b * 2048 + tid];
    hist[tid + 1024] = g_hist1[b * 2048 + 1024 + tid];
    __syncthreads();
    {
        if (tid < 64) {
            int s = 0;
            #pragma unroll
            for (int j = 0; j < 32; j++) s += hist[tid * 32 + j];
            s_group[tid] = s;
        }
        __syncthreads();
        if (tid == 0) {
            int cum = 0, g = 63;
            for (; g > 0; g--) {
                if (cum + s_group[g] >= kk) break;
                cum += s_group[g];
            }
            int x = g * 32 + 31;
            for (;; x--) {
                int hv = hist[x];
                if (cum + hv >= kk || x == g * 32) break;
                cum += hv;
            }
            s_prefix = ((unsigned)x << 21);
            s_kk = kk - cum;
        }
        __syncthreads();
        prefix = s_prefix;
        kk     = s_kk;
    }

    // ---- passes 2 & 3: sweeps ----
    const int shifts[2] = {10, 0};
    const int nbits [2] = {11, 10};
    #pragma unroll
    for (int pass = 0; pass < 2; pass++) {
        const int shift = shifts[pass];
        const int nb    = 1 << nbits[pass];
        hist[tid] = 0; hist[tid + 1024] = 0;
        __syncthreads();
        const unsigned hmask = 0xFFFFFFFFu << (shift + nbits[pass]);
        const unsigned bmask = (unsigned)(nb - 1);

        int i = tid;
        for (; i + 7 * 1024 < PP; i += 8 * 1024) {
            unsigned kx[8];
            #pragma unroll
            for (int u = 0; u < 8; u++) kx[u] = __float_as_uint(lc[i + u * 1024]);
            #pragma unroll
            for (int u = 0; u < 8; u++)
                if ((kx[u] & hmask) == prefix) atomicAdd(&hist[(kx[u] >> shift) & bmask], 1);
        }
        for (; i < PP; i += 1024) {
            unsigned key = __float_as_uint(lc[i]);
            if ((key & hmask) == prefix) atomicAdd(&hist[(key >> shift) & bmask], 1);
        }
        __syncthreads();

        const int ngroups = nb >> 5;
        if (tid < ngroups) {
            int s = 0;
            #pragma unroll
            for (int j = 0; j < 32; j++) s += hist[tid * 32 + j];
            s_group[tid] = s;
        }
        __syncthreads();
        if (tid == 0) {
            int cum = 0, g = ngroups - 1;
            for (; g > 0; g--) {
                if (cum + s_group[g] >= kk) break;
                cum += s_group[g];
            }
            int x = g * 32 + 31;
            for (;; x--) {
                int hv = hist[x];
                if (cum + hv >= kk || x == g * 32) break;
                cum += hv;
            }
            s_prefix = prefix | ((unsigned)x << shift);
            s_kk = kk - cum;
        }
        __syncthreads();
        prefix = s_prefix;
        kk     = s_kk;
    }

    float  thr   = __uint_as_float(prefix);
    double local = 0.0;
    {
        int i = tid;
        for (; i + 7 * 1024 < PP; i += 8 * 1024) {
            float a[8];
            #pragma unroll
            for (int u = 0; u < 8; u++) a[u] = lc[i + u * 1024];
            #pragma unroll
            for (int u = 0; u < 8; u++)
                if (__float_as_uint(a[u]) > prefix) local += (double)a[u];
        }
        for (; i < PP; i += 1024) {
            float v = lc[i];
            if (__float_as_uint(v) > prefix) local += (double)v;
        }
    }
    #pragma unroll
    for (int o = 16; o > 0; o >>= 1) local += __shfl_xor_sync(0xffffffffu, local, o);
    __shared__ double sdl[32];
    int lane = tid & 31, w = tid >> 5;
    if (lane == 0) sdl[w] = local;
    __syncthreads();
    if (tid == 0) {
        double tot = 0.0;
        for (int i = 0; i < 32; i++) tot += sdl[i];
        tot += (double)kk * (double)thr;
        atomicAdd(&g_ce_neg, tot);
    }
}

// ---------------- finalize ----------------
__global__ void final_kernel(float* out) {
    double N = (double)g_total_pos;
    if (N < 1.0) N = 1.0;
    out[0] = (float)(g_loss_l / N);
    out[1] = (float)((g_ce_pos + g_ce_neg) / N);
}

extern "C" void kernel_launch(void* const* d_in, const int* in_sizes, int n_in,
                              void* d_out, int out_size) {
    const float* loc_data  = (const float*)d_in[0];   // [B,P,4]
    const float* conf_data = (const float*)d_in[1];   // [B,P,81]
    const float* priors    = (const float*)d_in[2];   // [P,4]
    const float* targets   = (const float*)d_in[3];   // [B,T,5]
    float* out = (float*)d_out;

    init_kernel<<<BB, 1024>>>();
    match_kernel<<<dim3((PP + 255) / 256, BB), 256>>>(priors, targets);
    force_kernel<<<1, BB>>>();
    loss_kernel<<<dim3(LNBX, BB), 128>>>(loc_data, conf_data, priors, targets);
    mine_kernel<<<BB, 1024>>>();
    final_kernel<<<1, 1>>>(out);
}

// round 8
// speedup vs baseline: 2.6456x; 1.0642x over previous
#include <cuda_runtime.h>
#include <cstdint>

#define BB 64
#define PP 25000
#define TT 16
#define CC 81

#define LROWS 64
#define LTILES 8
#define NTILE ((PP + LROWS - 1) / LROWS)          // 391
#define LNBX ((NTILE + LTILES - 1) / LTILES)      // 49

// ---------------- scratch ----------------
__device__ float               g_bt_ov[BB * PP + 64];   // +64 pad: stage prefetch overrun
__device__ unsigned char       g_bt_idx[BB * PP + 64];
__device__ unsigned long long  g_bp_key[BB * TT];
__device__ float               g_loss_c[BB * PP];
__device__ int                 g_hist1[BB * 2048];
__device__ int                 g_num_pos[BB];
__device__ int                 g_total_pos;
__device__ double              g_loss_l;
__device__ double              g_ce_pos;
__device__ double              g_ce_neg;

// ---------------- cp.async helpers ----------------
__device__ __forceinline__ void cp_async16(void* smem, const void* gmem) {
    unsigned saddr = (unsigned)__cvta_generic_to_shared(smem);
    asm volatile("cp.async.cg.shared.global [%0], [%1], 16;" :: "r"(saddr), "l"(gmem));
}
__device__ __forceinline__ void cp_async8(void* smem, const void* gmem) {
    unsigned saddr = (unsigned)__cvta_generic_to_shared(smem);
    asm volatile("cp.async.ca.shared.global [%0], [%1], 8;" :: "r"(saddr), "l"(gmem));
}
__device__ __forceinline__ void cp_commit() {
    asm volatile("cp.async.commit_group;");
}
template <int N>
__device__ __forceinline__ void cp_wait() {
    asm volatile("cp.async.wait_group %0;" :: "n"(N));
}

// ---------------- init ----------------
__global__ void init_kernel() {
    int b = blockIdx.x, tid = threadIdx.x;
    g_hist1[b * 2048 + tid] = 0;
    g_hist1[b * 2048 + 1024 + tid] = 0;
    if (b == 0) {
        g_bp_key[tid] = 0ULL;                      // BB*TT == 1024
        if (tid < BB) g_num_pos[tid] = 0;
        if (tid == 0) { g_total_pos = 0; g_loss_l = 0.0; g_ce_pos = 0.0; g_ce_neg = 0.0; }
    }
}

// ---------------- match ----------------
__global__ void match_kernel(const float* __restrict__ priors,
                             const float* __restrict__ targets) {
    const int b = blockIdx.y;
    const int p = blockIdx.x * 256 + threadIdx.x;
    const int lane = threadIdx.x & 31;
    __shared__ float s_t[TT][4];
    __shared__ float s_ta[TT];
    __shared__ unsigned long long s_key[TT];

    if (threadIdx.x < TT) {
        const float* tr = targets + ((size_t)b * TT + threadIdx.x) * 5;
        float x0 = tr[0], y0 = tr[1], x1 = tr[2], y1 = tr[3];
        s_t[threadIdx.x][0] = x0; s_t[threadIdx.x][1] = y0;
        s_t[threadIdx.x][2] = x1; s_t[threadIdx.x][3] = y1;
        s_ta[threadIdx.x] = (x1 - x0) * (y1 - y0);
        s_key[threadIdx.x] = 0ULL;
    }
    __syncthreads();

    const bool valid = (p < PP);
    float px0 = 0.f, py0 = 0.f, px1 = 0.f, py1 = 0.f, pa = 0.f;
    if (valid) {
        float4 pr = ((const float4*)priors)[p];
        px0 = pr.x - pr.z * 0.5f; py0 = pr.y - pr.w * 0.5f;
        px1 = pr.x + pr.z * 0.5f; py1 = pr.y + pr.w * 0.5f;
        pa  = (px1 - px0) * (py1 - py0);
    }

    float best = -1.0f;
    int   bi   = 0;

    #pragma unroll
    for (int t = 0; t < TT; t++) {
        unsigned ib = 0;
        if (valid) {
            float lx = fmaxf(s_t[t][0], px0), ly = fmaxf(s_t[t][1], py0);
            float rx = fminf(s_t[t][2], px1), ry = fminf(s_t[t][3], py1);
            float iw = fmaxf(rx - lx, 0.0f), ih = fmaxf(ry - ly, 0.0f);
            float inter = iw * ih;
            float iou = inter / (s_ta[t] + pa - inter);
            if (iou > best) { best = iou; bi = t; }           // strict > -> first max
            ib = __float_as_uint(iou);                        // iou >= 0 -> order-preserving
        }
        unsigned wmax = __reduce_max_sync(0xffffffffu, ib);
        unsigned cp   = (valid && ib == wmax) ? (unsigned)p : 0xFFFFFFFFu;
        unsigned pmin = __reduce_min_sync(0xffffffffu, cp);
        if (lane == 0) {
            unsigned long long key = (((unsigned long long)wmax) << 32) | (unsigned)(~pmin);
            atomicMax(&s_key[t], key);
        }
    }

    if (valid) {
        g_bt_ov[(size_t)b * PP + p]  = best;
        g_bt_idx[(size_t)b * PP + p] = (unsigned char)bi;
    }
    __syncthreads();
    if (threadIdx.x < TT) atomicMax(&g_bp_key[b * TT + threadIdx.x], s_key[threadIdx.x]);
}

// ---------------- force each truth's best prior (last j wins) ----------------
__global__ void force_kernel() {
    int b = threadIdx.x;
    if (b >= BB) return;
    for (int j = 0; j < TT; j++) {
        unsigned long long key = g_bp_key[b * TT + j];
        unsigned p = ~(unsigned)(key & 0xFFFFFFFFULL);
        g_bt_ov[(size_t)b * PP + p]  = 2.0f;
        g_bt_idx[(size_t)b * PP + p] = (unsigned char)j;
    }
}

// ---------------- fused loss: 256 threads, cp.async double buffer ----------------
// 4-row strips (324 floats, float4-aligned); 16 threads/strip: thread h covers
// floats [20h, 20h+20) (h15: [300,324) = 6 float4s). <=1 row boundary each.
__global__ void __launch_bounds__(256, 5) loss_kernel(
        const float* __restrict__ loc_data,
        const float* __restrict__ conf_data,
        const float* __restrict__ priors,
        const float* __restrict__ targets) {
    const int b   = blockIdx.y;
    const int tid = threadIdx.x;
    const int t0  = blockIdx.x * LTILES;
    const int S   = min(LTILES, NTILE - t0);

    __shared__ float         s_buf[2][LROWS * CC];   // 2 x 20736 B
    __shared__ float         s_ov[2][LROWS];
    __shared__ unsigned char s_ti[2][LROWS];
    __shared__ float         s_pa[256], s_pb[256];
    __shared__ float         s_tr[TT][5];
    __shared__ float         s_ll[8], s_cep[8];
    __shared__ int           s_pos[8];

    if (tid < TT * 5)
        ((float*)s_tr)[tid] = targets[(size_t)b * TT * 5 + tid];

    const float* cbase = conf_data + (size_t)b * PP * CC;
    const float* ovbase = g_bt_ov + (size_t)b * PP;
    const unsigned char* tibase = g_bt_idx + (size_t)b * PP;

    // prefetch stage 0 (conf + ov + idx)
    {
        const int row0 = t0 * LROWS;
        const int nf4  = (min(LROWS, PP - row0) * CC) >> 2;
        const float4* g4 = (const float4*)(cbase + (size_t)row0 * CC);
        float4* s4 = (float4*)s_buf[0];
        for (int i = tid; i < nf4; i += 256) cp_async16(s4 + i, g4 + i);
        if (tid < 16) cp_async16((float4*)s_ov[0] + tid, (const float4*)(ovbase + row0) + tid);
        else if (tid < 24) cp_async8((double*)s_ti[0] + (tid - 16),
                                     (const double*)(tibase + row0) + (tid - 16));
        cp_commit();
    }

    float my_ll = 0.f, my_cep = 0.f;
    int   my_pos = 0;

    const int st  = tid >> 4;                 // strip 0..15
    const int h   = tid & 15;
    const int fs  = 20 * h;                   // first float in strip
    const int nf  = (h == 15) ? 6 : 5;        // float4 count
    const int fe  = fs + 4 * nf;
    const int rAx = fs / 81;                  // row of first float
    const int splitf = min((rAx + 1) * 81, fe);

    for (int s = 0; s < S; s++) {
        if (s + 1 < S) {
            const int row0 = (t0 + s + 1) * LROWS;
            const int nf4  = (min(LROWS, PP - row0) * CC) >> 2;
            const float4* g4 = (const float4*)(cbase + (size_t)row0 * CC);
            float4* s4 = (float4*)s_buf[(s + 1) & 1];
            for (int i = tid; i < nf4; i += 256) cp_async16(s4 + i, g4 + i);
            if (tid < 16) cp_async16((float4*)s_ov[(s + 1) & 1] + tid,
                                     (const float4*)(ovbase + row0) + tid);
            else if (tid < 24) cp_async8((double*)s_ti[(s + 1) & 1] + (tid - 16),
                                         (const double*)(tibase + row0) + (tid - 16));
            cp_commit();
            cp_wait<1>();
        } else {
            cp_wait<0>();
        }
        __syncthreads();

        const int row0 = (t0 + s) * LROWS;
        const int n    = min(LROWS, PP - row0);
        const float* base = s_buf[s & 1];

        float accA = 0.f, accB = 0.f;
        if (st * 4 < n) {
            const float* tp = base + st * 324 + fs;
            #pragma unroll
            for (int i = 0; i < 6; i++) {
                if (i < nf) {
                    float4 v = *(const float4*)(tp + 4 * i);
                    float e0 = __expf(v.x), e1 = __expf(v.y);
                    float e2 = __expf(v.z), e3 = __expf(v.w);
                    float sv = (e0 + e1) + (e2 + e3);
                    int w = fs + 4 * i;
                    if (w + 4 <= splitf)      accA += sv;
                    else if (w >= splitf)     accB += sv;
                    else {
                        accA += (w     < splitf ? e0 : 0.f) + (w + 1 < splitf ? e1 : 0.f)
                              + (w + 2 < splitf ? e2 : 0.f) + (w + 3 < splitf ? e3 : 0.f);
                        accB += (w     >= splitf ? e0 : 0.f) + (w + 1 >= splitf ? e1 : 0.f)
                              + (w + 2 >= splitf ? e2 : 0.f) + (w + 3 >= splitf ? e3 : 0.f);
                    }
                }
            }
        }
        s_pa[tid] = accA; s_pb[tid] = accB;
        __syncthreads();

        if (tid < n) {
            const int ss = tid >> 2, r = tid & 3;
            const float* pa = s_pa + ss * 16;
            const float* pb = s_pb + ss * 16;
            float tot = (r == 0) ? pa[0] + pa[1] + pa[2] + pa[3] + pa[4]
                      : (r == 1) ? pb[4] + pa[5] + pa[6] + pa[7] + pa[8]
                      : (r == 2) ? pb[8] + pa[9] + pa[10] + pa[11] + pa[12]
                      :            pb[12] + pa[13] + pa[14] + pa[15];
            const int p = row0 + tid;
            float lse = __logf(tot);
            float ov = s_ov[s & 1][tid];
            int   ti = s_ti[s & 1][tid];
            bool pos = (ov >= 0.5f);
            int  ct  = pos ? ((int)s_tr[ti][4] + 1) : 0;
            float ce = lse - base[tid * 81 + ct];
            float lc = pos ? 0.f : ce;
            g_loss_c[(size_t)b * PP + p] = lc;
            atomicAdd(&g_hist1[b * 2048 + (int)(__float_as_uint(lc) >> 21)], 1);
            if (pos) {
                my_pos++;
                my_cep += ce;
                float4 pr = ((const float4*)priors)[p];
                float tx0 = s_tr[ti][0], ty0 = s_tr[ti][1];
                float tx1 = s_tr[ti][2], ty1 = s_tr[ti][3];
                float gx = ((tx0 + tx1) * 0.5f - pr.x) / (0.1f * pr.z);
                float gy = ((ty0 + ty1) * 0.5f - pr.y) / (0.1f * pr.w);
                float gw = __logf((tx1 - tx0) / pr.z) * 5.0f;
                float gh = __logf((ty1 - ty0) / pr.w) * 5.0f;
                float4 ld = ((const float4*)loc_data)[(size_t)b * PP + p];
                float d, ad;
                d = ld.x - gx; ad = fabsf(d); my_ll += (ad < 1.f) ? 0.5f * d * d : ad - 0.5f;
                d = ld.y - gy; ad = fabsf(d); my_ll += (ad < 1.f) ? 0.5f * d * d : ad - 0.5f;
                d = ld.z - gw; ad = fabsf(d); my_ll += (ad < 1.f) ? 0.5f * d * d : ad - 0.5f;
                d = ld.w - gh; ad = fabsf(d); my_ll += (ad < 1.f) ? 0.5f * d * d : ad - 0.5f;
            }
        }
        __syncthreads();
    }

    // ---- block reduce (8 warps) ----
    #pragma unroll
    for (int o = 16; o > 0; o >>= 1) {
        my_ll  += __shfl_xor_sync(0xffffffffu, my_ll, o);
        my_cep += __shfl_xor_sync(0xffffffffu, my_cep, o);
        my_pos += __shfl_xor_sync(0xffffffffu, my_pos, o);
    }
    const int lane = tid & 31, warp = tid >> 5;
    if (lane == 0) { s_ll[warp] = my_ll; s_cep[warp] = my_cep; s_pos[warp] = my_pos; }
    __syncthreads();
    if (tid == 0) {
        float ll = 0.f, cep = 0.f; int np = 0;
        #pragma unroll
        for (int w = 0; w < 8; w++) { ll += s_ll[w]; cep += s_cep[w]; np += s_pos[w]; }
        if (np) {
            atomicAdd(&g_loss_l, (double)ll);
            atomicAdd(&g_ce_pos, (double)cep);
            atomicAdd(&g_num_pos[b], np);
            atomicAdd(&g_total_pos, np);
        }
    }
}

// ---------------- mining: pass1 from precomputed hist, then 2 radix sweeps ----------------
__global__ void mine_kernel() {
    const int b   = blockIdx.x;
    const int tid = threadIdx.x;
    __shared__ int      hist[2048];
    __shared__ int      s_group[64];
    __shared__ unsigned s_prefix;
    __shared__ int      s_kk;

    int np = g_num_pos[b];
    int k  = min(3 * np, PP - 1);
    if (k <= 0) return;  // uniform across block

    const float* lc = g_loss_c + (size_t)b * PP;
    unsigned prefix = 0;
    int kk = k;

    // ---- pass 1: precomputed histogram (bits 31..21) ----
    hist[tid] = g_hist1[b * 2048 + tid];
    hist[tid + 1024] = g_hist1[b * 2048 + 1024 + tid];
    __syncthreads();
    {
        if (tid < 64) {
            int s = 0;
            #pragma unroll
            for (int j = 0; j < 32; j++) s += hist[tid * 32 + j];
            s_group[tid] = s;
        }
        __syncthreads();
        if (tid == 0) {
            int cum = 0, g = 63;
            for (; g > 0; g--) {
                if (cum + s_group[g] >= kk) break;
                cum += s_group[g];
            }
            int x = g * 32 + 31;
            for (;; x--) {
                int hv = hist[x];
                if (cum + hv >= kk || x == g * 32) break;
                cum += hv;
            }
            s_prefix = ((unsigned)x << 21);
            s_kk = kk - cum;
        }
        __syncthreads();
        prefix = s_prefix;
        kk     = s_kk;
    }

    // ---- passes 2 & 3 ----
    const int shifts[2] = {10, 0};
    const int nbits [2] = {11, 10};
    #pragma unroll
    for (int pass = 0; pass < 2; pass++) {
        const int shift = shifts[pass];
        const int nb    = 1 << nbits[pass];
        hist[tid] = 0; hist[tid + 1024] = 0;
        __syncthreads();
        const unsigned hmask = 0xFFFFFFFFu << (shift + nbits[pass]);
        const unsigned bmask = (unsigned)(nb - 1);

        int i = tid;
        for (; i + 7 * 1024 < PP; i += 8 * 1024) {
            unsigned kx[8];
            #pragma unroll
            for (int u = 0; u < 8; u++) kx[u] = __float_as_uint(lc[i + u * 1024]);
            #pragma unroll
            for (int u = 0; u < 8; u++)
                if ((kx[u] & hmask) == prefix) atomicAdd(&hist[(kx[u] >> shift) & bmask], 1);
        }
        for (; i < PP; i += 1024) {
            unsigned key = __float_as_uint(lc[i]);
            if ((key & hmask) == prefix) atomicAdd(&hist[(key >> shift) & bmask], 1);
        }
        __syncthreads();

        const int ngroups = nb >> 5;
        if (tid < ngroups) {
            int s = 0;
            #pragma unroll
            for (int j = 0; j < 32; j++) s += hist[tid * 32 + j];
            s_group[tid] = s;
        }
        __syncthreads();
        if (tid == 0) {
            int cum = 0, g = ngroups - 1;
            for (; g > 0; g--) {
                if (cum + s_group[g] >= kk) break;
                cum += s_group[g];
            }
            int x = g * 32 + 31;
            for (;; x--) {
                int hv = hist[x];
                if (cum + hv >= kk || x == g * 32) break;
                cum += hv;
            }
            s_prefix = prefix | ((unsigned)x << shift);
            s_kk = kk - cum;
        }
        __syncthreads();
        prefix = s_prefix;
        kk     = s_kk;
    }

    float  thr   = __uint_as_float(prefix);
    double local = 0.0;
    {
        int i = tid;
        for (; i + 7 * 1024 < PP; i += 8 * 1024) {
            float a[8];
            #pragma unroll
            for (int u = 0; u < 8; u++) a[u] = lc[i + u * 1024];
            #pragma unroll
            for (int u = 0; u < 8; u++)
                if (__float_as_uint(a[u]) > prefix) local += (double)a[u];
        }
        for (; i < PP; i += 1024) {
            float v = lc[i];
            if (__float_as_uint(v) > prefix) local += (double)v;
        }
    }
    #pragma unroll
    for (int o = 16; o > 0; o >>= 1) local += __shfl_xor_sync(0xffffffffu, local, o);
    __shared__ double sdl[32];
    int lane = tid & 31, w = tid >> 5;
    if (lane == 0) sdl[w] = local;
    __syncthreads();
    if (tid == 0) {
        double tot = 0.0;
        for (int i = 0; i < 32; i++) tot += sdl[i];
        tot += (double)kk * (double)thr;
        atomicAdd(&g_ce_neg, tot);
    }
}

// ---------------- finalize ----------------
__global__ void final_kernel(float* out) {
    double N = (double)g_total_pos;
    if (N < 1.0) N = 1.0;
    out[0] = (float)(g_loss_l / N);
    out[1] = (float)((g_ce_pos + g_ce_neg) / N);
}

extern "C" void kernel_launch(void* const* d_in, const int* in_sizes, int n_in,
                              void* d_out, int out_size) {
    const float* loc_data  = (const float*)d_in[0];   // [B,P,4]
    const float* conf_data = (const float*)d_in[1];   // [B,P,81]
    const float* priors    = (const float*)d_in[2];   // [P,4]
    const float* targets   = (const float*)d_in[3];   // [B,T,5]
    float* out = (float*)d_out;

    init_kernel<<<BB, 1024>>>();
    match_kernel<<<dim3((PP + 255) / 256, BB), 256>>>(priors, targets);
    force_kernel<<<1, BB>>>();
    loss_kernel<<<dim3(LNBX, BB), 256>>>(loc_data, conf_data, priors, targets);
    mine_kernel<<<BB, 1024>>>();
    final_kernel<<<1, 1>>>(out);
}

// round 9
// speedup vs baseline: 2.6544x; 1.0033x over previous
#include <cuda_runtime.h>
#include <cstdint>

#define BB 64
#define PP 25000
#define TT 16
#define CC 81

#define LROWS 64
#define LTILES 8
#define NTILE ((PP + LROWS - 1) / LROWS)          // 391
#define LNBX ((NTILE + LTILES - 1) / LTILES)      // 49

// ---------------- scratch ----------------
__device__ float               g_bt_ov[BB * PP];
__device__ unsigned char       g_bt_idx[BB * PP];
__device__ unsigned long long  g_bp_key[BB * TT];
__device__ float               g_loss_c[BB * PP];
__device__ int                 g_hist1[BB * 2048];
__device__ int                 g_num_pos[BB];
__device__ int                 g_total_pos;
__device__ double              g_loss_l;
__device__ double              g_ce_pos;
__device__ double              g_ce_neg;

// ---------------- async helpers ----------------
__device__ __forceinline__ unsigned smem_u32(const void* p) {
    return (unsigned)__cvta_generic_to_shared(p);
}
__device__ __forceinline__ void mbar_init(unsigned mbar, unsigned count) {
    asm volatile("mbarrier.init.shared.b64 [%0], %1;" :: "r"(mbar), "r"(count) : "memory");
}
__device__ __forceinline__ void mbar_expect_tx(unsigned mbar, unsigned bytes) {
    asm volatile("mbarrier.arrive.expect_tx.shared.b64 _, [%0], %1;"
                 :: "r"(mbar), "r"(bytes) : "memory");
}
__device__ __forceinline__ void bulk_g2s(unsigned dst, const void* src,
                                         unsigned bytes, unsigned mbar) {
    asm volatile("cp.async.bulk.shared::cluster.global.mbarrier::complete_tx::bytes "
                 "[%0], [%1], %2, [%3];"
                 :: "r"(dst), "l"(src), "r"(bytes), "r"(mbar) : "memory");
}
__device__ __forceinline__ void mbar_wait(unsigned mbar, unsigned parity) {
    asm volatile(
        "{\n\t.reg .pred P;\n\t"
        "WL%=:\n\t"
        "mbarrier.try_wait.parity.acquire.cta.shared::cta.b64 P, [%0], %1, 0x989680;\n\t"
        "@P bra.uni WD%=;\n\t"
        "bra.uni WL%=;\n\t"
        "WD%=:\n\t}"
        :: "r"(mbar), "r"(parity) : "memory");
}

// ---------------- match ----------------
__global__ void match_kernel(const float* __restrict__ priors,
                             const float* __restrict__ targets) {
    const int b = blockIdx.y;
    const int p = blockIdx.x * 256 + threadIdx.x;
    const int lane = threadIdx.x & 31;
    __shared__ float s_t[TT][4];
    __shared__ float s_ta[TT];
    __shared__ unsigned long long s_key[TT];

    if (threadIdx.x < TT) {
        const float* tr = targets + ((size_t)b * TT + threadIdx.x) * 5;
        float x0 = tr[0], y0 = tr[1], x1 = tr[2], y1 = tr[3];
        s_t[threadIdx.x][0] = x0; s_t[threadIdx.x][1] = y0;
        s_t[threadIdx.x][2] = x1; s_t[threadIdx.x][3] = y1;
        s_ta[threadIdx.x] = (x1 - x0) * (y1 - y0);
        s_key[threadIdx.x] = 0ULL;
    }
    __syncthreads();

    const bool valid = (p < PP);
    float px0 = 0.f, py0 = 0.f, px1 = 0.f, py1 = 0.f, pa = 0.f;
    if (valid) {
        float4 pr = ((const float4*)priors)[p];
        px0 = pr.x - pr.z * 0.5f; py0 = pr.y - pr.w * 0.5f;
        px1 = pr.x + pr.z * 0.5f; py1 = pr.y + pr.w * 0.5f;
        pa  = (px1 - px0) * (py1 - py0);
    }

    float best = -1.0f;
    int   bi   = 0;

    #pragma unroll
    for (int t = 0; t < TT; t++) {
        unsigned ib = 0;
        if (valid) {
            float lx = fmaxf(s_t[t][0], px0), ly = fmaxf(s_t[t][1], py0);
            float rx = fminf(s_t[t][2], px1), ry = fminf(s_t[t][3], py1);
            float iw = fmaxf(rx - lx, 0.0f), ih = fmaxf(ry - ly, 0.0f);
            float inter = iw * ih;
            float iou = inter / (s_ta[t] + pa - inter);
            if (iou > best) { best = iou; bi = t; }           // strict > -> first max
            ib = __float_as_uint(iou);                        // iou >= 0 -> order-preserving
        }
        unsigned wmax = __reduce_max_sync(0xffffffffu, ib);
        unsigned cp   = (valid && ib == wmax) ? (unsigned)p : 0xFFFFFFFFu;
        unsigned pmin = __reduce_min_sync(0xffffffffu, cp);
        if (lane == 0) {
            unsigned long long key = (((unsigned long long)wmax) << 32) | (unsigned)(~pmin);
            atomicMax(&s_key[t], key);
        }
    }

    if (valid) {
        g_bt_ov[(size_t)b * PP + p]  = best;
        g_bt_idx[(size_t)b * PP + p] = (unsigned char)bi;
    }
    __syncthreads();
    if (threadIdx.x < TT) atomicMax(&g_bp_key[b * TT + threadIdx.x], s_key[threadIdx.x]);
}

// ---------------- force each truth's best prior (last j wins) ----------------
__global__ void force_kernel() {
    int b = threadIdx.x;
    if (b >= BB) return;
    for (int j = 0; j < TT; j++) {
        unsigned long long key = g_bp_key[b * TT + j];
        unsigned p = ~(unsigned)(key & 0xFFFFFFFFULL);
        g_bt_ov[(size_t)b * PP + p]  = 2.0f;
        g_bt_idx[(size_t)b * PP + p] = (unsigned char)j;
    }
}

// ---------------- fused loss: bulk-copy double buffer + shuffle combine ----------------
// 4-row strips (324 floats); 16 threads/strip (half-warp): thread h covers floats
// [20h, 20h+20) (h15: 24). Row sums combined via intra-half-warp shuffles; row
// leaders (h % 4 == 0) run the epilogue for row r = h/4.
__global__ void __launch_bounds__(256, 5) loss_kernel(
        const float* __restrict__ loc_data,
        const float* __restrict__ conf_data,
        const float* __restrict__ priors,
        const float* __restrict__ targets) {
    const int b   = blockIdx.y;
    const int tid = threadIdx.x;
    const int t0  = blockIdx.x * LTILES;
    const int S   = min(LTILES, NTILE - t0);

    __shared__ float s_buf[2][LROWS * CC];                 // 2 x 20736 B
    __shared__ float s_tr[TT][5];
    __shared__ float s_ll[8], s_cep[8];
    __shared__ int   s_pos[8];
    __shared__ __align__(8) unsigned long long s_mbar[2];

    if (tid < TT * 5)
        ((float*)s_tr)[tid] = targets[(size_t)b * TT * 5 + tid];

    const unsigned mb[2]  = { smem_u32(&s_mbar[0]), smem_u32(&s_mbar[1]) };
    const unsigned sb[2]  = { smem_u32(&s_buf[0][0]), smem_u32(&s_buf[1][0]) };
    if (tid == 0) { mbar_init(mb[0], 1); mbar_init(mb[1], 1); }
    __syncthreads();

    const float* cbase = conf_data + (size_t)b * PP * CC;

    // produce stage 0
    if (tid == 0) {
        const int row0 = t0 * LROWS;
        const unsigned bytes = (unsigned)(min(LROWS, PP - row0) * CC * 4);
        mbar_expect_tx(mb[0], bytes);
        bulk_g2s(sb[0], cbase + (size_t)row0 * CC, bytes, mb[0]);
    }

    float my_ll = 0.f, my_cep = 0.f;
    int   my_pos = 0;

    const int strip_l = tid >> 4;                 // strip within stage (0..15)
    const int h       = tid & 15;
    const int fs      = 20 * h;
    const int nf      = (h == 15) ? 6 : 5;
    const int fe      = fs + 4 * nf;
    const int splitf  = min((fs / 81 + 1) * 81, fe);
    const int r       = h >> 2;                   // row within strip for leaders
    const bool rowlead = ((h & 3) == 0);

    for (int s = 0; s < S; s++) {
        // produce stage s+1 (buffer freed by end-of-(s-1) syncthreads)
        if (s + 1 < S && tid == 0) {
            const int row0n = (t0 + s + 1) * LROWS;
            const unsigned bytes = (unsigned)(min(LROWS, PP - row0n) * CC * 4);
            mbar_expect_tx(mb[(s + 1) & 1], bytes);
            bulk_g2s(sb[(s + 1) & 1], cbase + (size_t)row0n * CC, bytes, mb[(s + 1) & 1]);
        }

        const int row0 = (t0 + s) * LROWS;
        const int rows = min(LROWS, PP - row0);   // 64 or 40 (both multiples of 4)
        const bool sact = (strip_l * 4 < rows);
        const int  prow = row0 + strip_l * 4 + r;

        // prefetch ov/ti (independent of conf data)
        float ovv = 0.f; int tiv = 0;
        if (rowlead && sact) {
            const size_t off = (size_t)b * PP + prow;
            ovv = g_bt_ov[off];
            tiv = g_bt_idx[off];
        }

        mbar_wait(mb[s & 1], (unsigned)((s >> 1) & 1));

        const float* base = s_buf[s & 1];
        float accA = 0.f, accB = 0.f;
        if (sact) {
            const float* tp = base + strip_l * 324 + fs;
            #pragma unroll
            for (int i = 0; i < 6; i++) {
                if (i < nf) {
                    float4 v = *(const float4*)(tp + 4 * i);
                    float e0 = __expf(v.x), e1 = __expf(v.y);
                    float e2 = __expf(v.z), e3 = __expf(v.w);
                    float sv = (e0 + e1) + (e2 + e3);
                    int w = fs + 4 * i;
                    if (w + 4 <= splitf)      accA += sv;
                    else if (w >= splitf)     accB += sv;
                    else {
                        accA += (w     < splitf ? e0 : 0.f) + (w + 1 < splitf ? e1 : 0.f)
                              + (w + 2 < splitf ? e2 : 0.f) + (w + 3 < splitf ? e3 : 0.f);
                        accB += (w     >= splitf ? e0 : 0.f) + (w + 1 >= splitf ? e1 : 0.f)
                              + (w + 2 >= splitf ? e2 : 0.f) + (w + 3 >= splitf ? e3 : 0.f);
                    }
                }
            }
        }

        // combine within half-warp: tot(r) = base + accA_{+1..+3} (+ accA_{+4} if r<3)
        float a1 = __shfl_down_sync(0xffffffffu, accA, 1);
        float a2 = __shfl_down_sync(0xffffffffu, accA, 2);
        float a3 = __shfl_down_sync(0xffffffffu, accA, 3);
        float a4 = __shfl_down_sync(0xffffffffu, accA, 4);
        float basev = (h == 0) ? accA : accB;
        float tot = basev + a1 + a2 + a3 + ((rowlead && r < 3) ? a4 : 0.f);

        if (rowlead && sact) {
            float lse = __logf(tot);
            bool pos = (ovv >= 0.5f);
            int  ct  = pos ? ((int)s_tr[tiv][4] + 1) : 0;
            float ce = lse - base[(strip_l * 4 + r) * 81 + ct];
            float lc = pos ? 0.f : ce;
            g_loss_c[(size_t)b * PP + prow] = lc;
            atomicAdd(&g_hist1[b * 2048 + (int)(__float_as_uint(lc) >> 21)], 1);
            if (pos) {
                my_pos++;
                my_cep += ce;
                float4 pr = ((const float4*)priors)[prow];
                float tx0 = s_tr[tiv][0], ty0 = s_tr[tiv][1];
                float tx1 = s_tr[tiv][2], ty1 = s_tr[tiv][3];
                float gx = ((tx0 + tx1) * 0.5f - pr.x) / (0.1f * pr.z);
                float gy = ((ty0 + ty1) * 0.5f - pr.y) / (0.1f * pr.w);
                float gw = __logf((tx1 - tx0) / pr.z) * 5.0f;
                float gh = __logf((ty1 - ty0) / pr.w) * 5.0f;
                float4 ld = ((const float4*)loc_data)[(size_t)b * PP + prow];
                float d, ad;
                d = ld.x - gx; ad = fabsf(d); my_ll += (ad < 1.f) ? 0.5f * d * d : ad - 0.5f;
                d = ld.y - gy; ad = fabsf(d); my_ll += (ad < 1.f) ? 0.5f * d * d : ad - 0.5f;
                d = ld.z - gw; ad = fabsf(d); my_ll += (ad < 1.f) ? 0.5f * d * d : ad - 0.5f;
                d = ld.w - gh; ad = fabsf(d); my_ll += (ad < 1.f) ? 0.5f * d * d : ad - 0.5f;
            }
        }
        __syncthreads();   // all done reading buf (s&1) before it is refilled at s+1
    }

    // ---- block reduce (8 warps) ----
    #pragma unroll
    for (int o = 16; o > 0; o >>= 1) {
        my_ll  += __shfl_xor_sync(0xffffffffu, my_ll, o);
        my_cep += __shfl_xor_sync(0xffffffffu, my_cep, o);
        my_pos += __shfl_xor_sync(0xffffffffu, my_pos, o);
    }
    const int lane = tid & 31, warp = tid >> 5;
    if (lane == 0) { s_ll[warp] = my_ll; s_cep[warp] = my_cep; s_pos[warp] = my_pos; }
    __syncthreads();
    if (tid == 0) {
        float ll = 0.f, cep = 0.f; int np = 0;
        #pragma unroll
        for (int w = 0; w < 8; w++) { ll += s_ll[w]; cep += s_cep[w]; np += s_pos[w]; }
        if (np) {
            atomicAdd(&g_loss_l, (double)ll);
            atomicAdd(&g_ce_pos, (double)cep);
            atomicAdd(&g_num_pos[b], np);
            atomicAdd(&g_total_pos, np);
        }
    }
}

// ---------------- mining: pass1 from precomputed hist, then 2 radix sweeps ----------------
__global__ void mine_kernel() {
    const int b   = blockIdx.x;
    const int tid = threadIdx.x;
    __shared__ int      hist[2048];
    __shared__ int      s_group[64];
    __shared__ unsigned s_prefix;
    __shared__ int      s_kk;

    int np = g_num_pos[b];
    int k  = min(3 * np, PP - 1);
    if (k <= 0) return;  // uniform across block

    const float* lc = g_loss_c + (size_t)b * PP;
    unsigned prefix = 0;
    int kk = k;

    // ---- pass 1: precomputed histogram (bits 31..21) ----
    hist[tid] = g_hist1[b * 2048 + tid];
    hist[tid + 1024] = g_hist1[b * 2048 + 1024 + tid];
    __syncthreads();
    {
        if (tid < 64) {
            int s = 0;
            #pragma unroll
            for (int j = 0; j < 32; j++) s += hist[tid * 32 + j];
            s_group[tid] = s;
        }
        __syncthreads();
        if (tid == 0) {
            int cum = 0, g = 63;
            for (; g > 0; g--) {
                if (cum + s_group[g] >= kk) break;
                cum += s_group[g];
            }
            int x = g * 32 + 31;
            for (;; x--) {
                int hv = hist[x];
                if (cum + hv >= kk || x == g * 32) break;
                cum += hv;
            }
            s_prefix = ((unsigned)x << 21);
            s_kk = kk - cum;
        }
        __syncthreads();
        prefix = s_prefix;
        kk     = s_kk;
    }

    // ---- passes 2 & 3 ----
    const int shifts[2] = {10, 0};
    const int nbits [2] = {11, 10};
    #pragma unroll
    for (int pass = 0; pass < 2; pass++) {
        const int shift = shifts[pass];
        const int nb    = 1 << nbits[pass];
        hist[tid] = 0; hist[tid + 1024] = 0;
        __syncthreads();
        const unsigned hmask = 0xFFFFFFFFu << (shift + nbits[pass]);
        const unsigned bmask = (unsigned)(nb - 1);

        int i = tid;
        for (; i + 7 * 1024 < PP; i += 8 * 1024) {
            unsigned kx[8];
            #pragma unroll
            for (int u = 0; u < 8; u++) kx[u] = __float_as_uint(lc[i + u * 1024]);
            #pragma unroll
            for (int u = 0; u < 8; u++)
                if ((kx[u] & hmask) == prefix) atomicAdd(&hist[(kx[u] >> shift) & bmask], 1);
        }
        for (; i < PP; i += 1024) {
            unsigned key = __float_as_uint(lc[i]);
            if ((key & hmask) == prefix) atomicAdd(&hist[(key >> shift) & bmask], 1);
        }
        __syncthreads();

        const int ngroups = nb >> 5;
        if (tid < ngroups) {
            int s = 0;
            #pragma unroll
            for (int j = 0; j < 32; j++) s += hist[tid * 32 + j];
            s_group[tid] = s;
        }
        __syncthreads();
        if (tid == 0) {
            int cum = 0, g = ngroups - 1;
            for (; g > 0; g--) {
                if (cum + s_group[g] >= kk) break;
                cum += s_group[g];
            }
            int x = g * 32 + 31;
            for (;; x--) {
                int hv = hist[x];
                if (cum + hv >= kk || x == g * 32) break;
                cum += hv;
            }
            s_prefix = prefix | ((unsigned)x << shift);
            s_kk = kk - cum;
        }
        __syncthreads();
        prefix = s_prefix;
        kk     = s_kk;
    }

    float  thr   = __uint_as_float(prefix);
    double local = 0.0;
    {
        int i = tid;
        for (; i + 7 * 1024 < PP; i += 8 * 1024) {
            float a[8];
            #pragma unroll
            for (int u = 0; u < 8; u++) a[u] = lc[i + u * 1024];
            #pragma unroll
            for (int u = 0; u < 8; u++)
                if (__float_as_uint(a[u]) > prefix) local += (double)a[u];
        }
        for (; i < PP; i += 1024) {
            float v = lc[i];
            if (__float_as_uint(v) > prefix) local += (double)v;
        }
    }
    #pragma unroll
    for (int o = 16; o > 0; o >>= 1) local += __shfl_xor_sync(0xffffffffu, local, o);
    __shared__ double sdl[32];
    int lane = tid & 31, w = tid >> 5;
    if (lane == 0) sdl[w] = local;
    __syncthreads();
    if (tid == 0) {
        double tot = 0.0;
        for (int i = 0; i < 32; i++) tot += sdl[i];
        tot += (double)kk * (double)thr;
        atomicAdd(&g_ce_neg, tot);
    }
}

// ---------------- finalize + cleanup for next replay ----------------
// Graph replays reuse device globals; zeroing here (after all reads) replaces
// the init kernel. First-ever run relies on static zero-initialization.
__global__ void final_kernel(float* out) {
    const int b = blockIdx.x, tid = threadIdx.x;
    if (b == 0 && tid == 0) {
        double N = (double)g_total_pos;
        if (N < 1.0) N = 1.0;
        out[0] = (float)(g_loss_l / N);
        out[1] = (float)((g_ce_pos + g_ce_neg) / N);
        g_total_pos = 0; g_loss_l = 0.0; g_ce_pos = 0.0; g_ce_neg = 0.0;
    }
    g_hist1[b * 2048 + tid] = 0;
    g_hist1[b * 2048 + 1024 + tid] = 0;
    if (b == 0) {
        g_bp_key[tid] = 0ULL;                       // BB*TT == 1024
        if (tid < BB) g_num_pos[tid] = 0;
    }
}

extern "C" void kernel_launch(void* const* d_in, const int* in_sizes, int n_in,
                              void* d_out, int out_size) {
    const float* loc_data  = (const float*)d_in[0];   // [B,P,4]
    const float* conf_data = (const float*)d_in[1];   // [B,P,81]
    const float* priors    = (const float*)d_in[2];   // [P,4]
    const float* targets   = (const float*)d_in[3];   // [B,T,5]
    float* out = (float*)d_out;

    match_kernel<<<dim3((PP + 255) / 256, BB), 256>>>(priors, targets);
    force_kernel<<<1, BB>>>();
    loss_kernel<<<dim3(LNBX, BB), 256>>>(loc_data, conf_data, priors, targets);
    mine_kernel<<<BB, 1024>>>();
    final_kernel<<<BB, 1024>>>(out);
}